// round 1
// baseline (speedup 1.0000x reference)
#include <cuda_runtime.h>
#include <cuda_bf16.h>

// Problem constants
#define Bsz 512
#define Hd  512
#define Km  6
#define Tt  60
#define OUTd 2
#define H2  1024
#define TO  120     // T*OUT
#define ROWS_PER_MODE (Bsz*Tt)      // 30720
#define NROWS (Km*Bsz*Tt)           // 184320
#define PRED_ELEMS (Bsz*Km*Tt*OUTd) // 368640

// ---------------- scratch (device globals; no runtime allocation) -------------
__device__ float g_comb[Bsz*3*Hd];          // (B, 3H)
__device__ float g_tmp1[Bsz*Hd];
__device__ float g_context[Bsz*Hd];
__device__ float g_v[Bsz*Hd];
__device__ float g_attn[Bsz*Hd];
__device__ float g_mf[Bsz*Km*Hd];           // (B,K,H)
__device__ float g_h[Bsz*Km*H2];            // (B,K,2H)
__device__ float g_coarse[Bsz*Km*TO];       // (B,K,T,OUT)
__device__ float g_c1[Bsz*Km*64];           // (B*K,64)
__device__ float g_x[(long long)Km*ROWS_PER_MODE*Hd]; // (K, B*T, H) refined feats
__device__ float g_r[(long long)Km*ROWS_PER_MODE*Hd]; // (K, B*T, H) gelu(x@Wr1)

__device__ __forceinline__ float gelu_exact(float x){
    return 0.5f * x * (1.0f + erff(x * 0.7071067811865476f));
}

#define ACT_NONE 0
#define ACT_GELU 1
#define ACT_RELU 2

// ---------------- generic tiled SGEMM: C = act(A@B + bias) --------------------
// A (M,K) row-major w/ lda + per-batch elem offset; B (K,N) row-major; C (M,N)
template<int ACT>
__global__ __launch_bounds__(256)
void sgemm_kernel(const float* __restrict__ A, long long sAb, int lda,
                  const float* __restrict__ Bm, long long sBb, int ldb,
                  const float* __restrict__ bias, long long sbias,
                  float* __restrict__ C, long long sCb, int ldc,
                  int M, int N, int Kd)
{
    constexpr int BM=128, BN=128, BK=8, TM=8, TN=8;
    __shared__ float As[BK][BM];
    __shared__ float Bs[BK][BN];
    const int bz = blockIdx.z;
    A  += (long long)bz * sAb;
    Bm += (long long)bz * sBb;
    C  += (long long)bz * sCb;
    const float* bptr = bias + (long long)bz * sbias;

    const int m0 = blockIdx.y * BM;
    const int n0 = blockIdx.x * BN;
    const int tid = threadIdx.x;
    const int trow = tid / 16, tcol = tid % 16;

    float acc[TM][TN];
    #pragma unroll
    for (int i=0;i<TM;i++)
        #pragma unroll
        for (int j=0;j<TN;j++) acc[i][j]=0.f;

    const int a_r = tid >> 1;            // 0..127
    const int a_c = (tid & 1) * 4;       // 0 or 4
    const int b_r = tid >> 5;            // 0..7
    const int b_c = (tid & 31) * 4;      // 0..124

    for (int k0 = 0; k0 < Kd; k0 += BK) {
        // A tile
        {
            int m = m0 + a_r;
            int kk = k0 + a_c;
            if (m < M && kk + 3 < Kd) {
                float4 va = *reinterpret_cast<const float4*>(&A[(long long)m*lda + kk]);
                As[a_c+0][a_r]=va.x; As[a_c+1][a_r]=va.y; As[a_c+2][a_r]=va.z; As[a_c+3][a_r]=va.w;
            } else {
                #pragma unroll
                for (int u=0;u<4;u++){
                    float vv = 0.f;
                    if (m < M && kk+u < Kd) vv = A[(long long)m*lda + kk+u];
                    As[a_c+u][a_r] = vv;
                }
            }
        }
        // B tile
        {
            int kk = k0 + b_r;
            int n = n0 + b_c;
            if (kk < Kd && n + 3 < N) {
                float4 vb = *reinterpret_cast<const float4*>(&Bm[(long long)kk*ldb + n]);
                Bs[b_r][b_c+0]=vb.x; Bs[b_r][b_c+1]=vb.y; Bs[b_r][b_c+2]=vb.z; Bs[b_r][b_c+3]=vb.w;
            } else {
                #pragma unroll
                for (int u=0;u<4;u++){
                    float vv = 0.f;
                    if (kk < Kd && n+u < N) vv = Bm[(long long)kk*ldb + n+u];
                    Bs[b_r][b_c+u] = vv;
                }
            }
        }
        __syncthreads();
        #pragma unroll
        for (int kk=0; kk<BK; kk++){
            float ar[TM], br[TN];
            #pragma unroll
            for (int i=0;i<TM;i++) ar[i] = As[kk][trow*TM+i];
            #pragma unroll
            for (int j=0;j<TN;j++) br[j] = Bs[kk][tcol*TN+j];
            #pragma unroll
            for (int i=0;i<TM;i++)
                #pragma unroll
                for (int j=0;j<TN;j++)
                    acc[i][j] = fmaf(ar[i], br[j], acc[i][j]);
        }
        __syncthreads();
    }

    #pragma unroll
    for (int i=0;i<TM;i++){
        int m = m0 + trow*TM + i;
        if (m >= M) continue;
        #pragma unroll
        for (int j=0;j<TN;j++){
            int n = n0 + tcol*TN + j;
            if (n >= N) continue;
            float val = acc[i][j] + bptr[n];
            if (ACT==ACT_GELU) val = gelu_exact(val);
            else if (ACT==ACT_RELU) val = fmaxf(val, 0.f);
            C[(long long)m*ldc + n] = val;
        }
    }
}

// ---------------- small elementwise kernels -----------------------------------
__global__ void build_combined_kernel(const float* __restrict__ a,
                                      const float* __restrict__ b,
                                      const float* __restrict__ c,
                                      float* __restrict__ comb)
{
    int idx = blockIdx.x*blockDim.x + threadIdx.x;
    if (idx >= Bsz*3*Hd) return;
    int row = idx / (3*Hd), col = idx % (3*Hd);
    float v;
    if (col < Hd) v = a[row*Hd + col];
    else if (col < 2*Hd) v = b[row*Hd + col - Hd];
    else v = c[row*Hd + col - 2*Hd];
    comb[idx] = v;
}

__global__ void build_mf_kernel(const float* __restrict__ mq,
                                const float* __restrict__ ctx,
                                float* __restrict__ mf)
{
    int idx = blockIdx.x*blockDim.x + threadIdx.x;
    if (idx >= Bsz*Km*Hd) return;
    int h = idx % Hd;
    int k = (idx / Hd) % Km;
    int b = idx / (Hd*Km);
    mf[idx] = mq[k*Hd + h] + ctx[b*Hd + h];
}

// Fused: traj = GELU(coarse@Wt + bt); u = traj + attn[b]; x = LayerNorm(u)
// One block (256 thr) per row; row = k*(B*T) + b*T + t ; output (K, B*T, H)
__global__ __launch_bounds__(256)
void traj_ln_kernel(const float* __restrict__ coarse,   // (B,K,T,2)
                    const float* __restrict__ attn,     // (B,H)
                    const float* __restrict__ Wt,       // (2,H)
                    const float* __restrict__ bt,       // (H)
                    const float* __restrict__ ln_g,
                    const float* __restrict__ ln_b,
                    float* __restrict__ X)
{
    const int row = blockIdx.x;
    const int k   = row / ROWS_PER_MODE;
    const int rem = row % ROWS_PER_MODE;
    const int b   = rem / Tt;
    const int t   = rem % Tt;
    const float c0 = coarse[((b*Km + k)*Tt + t)*OUTd + 0];
    const float c1 = coarse[((b*Km + k)*Tt + t)*OUTd + 1];
    const int tid = threadIdx.x;

    float u[2];
    float s = 0.f;
    #pragma unroll
    for (int q=0;q<2;q++){
        int h = tid + q*256;
        float pre = fmaf(c0, Wt[h], fmaf(c1, Wt[Hd + h], bt[h]));
        float uu = gelu_exact(pre) + attn[b*Hd + h];
        u[q] = uu;
        s += uu;
    }
    __shared__ float red[8];
    #pragma unroll
    for (int o=16;o>0;o>>=1) s += __shfl_xor_sync(0xffffffffu, s, o);
    if ((tid & 31) == 0) red[tid>>5] = s;
    __syncthreads();
    float mean;
    {
        float v = (tid < 8) ? red[tid] : 0.f;
        #pragma unroll
        for (int o=4;o>0;o>>=1) v += __shfl_xor_sync(0xffffffffu, v, o);
        mean = __shfl_sync(0xffffffffu, v, 0) * (1.f/512.f);
        mean = __shfl_sync(0xffffffffu, mean, 0);
    }
    // broadcast mean across all warps via smem
    __syncthreads();
    if (tid == 0) red[0] = mean;
    __syncthreads();
    mean = red[0];

    float vs = 0.f;
    #pragma unroll
    for (int q=0;q<2;q++){ float d = u[q] - mean; vs += d*d; }
    __syncthreads();
    #pragma unroll
    for (int o=16;o>0;o>>=1) vs += __shfl_xor_sync(0xffffffffu, vs, o);
    if ((tid & 31) == 0) red[tid>>5] = vs;
    __syncthreads();
    float rstd;
    if (tid < 32) {
        float v = (tid < 8) ? red[tid] : 0.f;
        #pragma unroll
        for (int o=4;o>0;o>>=1) v += __shfl_xor_sync(0xffffffffu, v, o);
        if (tid == 0) red[0] = rsqrtf(v * (1.f/512.f) + 1e-5f);
    }
    __syncthreads();
    rstd = red[0];

    float* xr = X + (long long)row * Hd;
    #pragma unroll
    for (int q=0;q<2;q++){
        int h = tid + q*256;
        xr[h] = (u[q] - mean) * rstd * ln_g[h] + ln_b[h];
    }
}

// offsets = r @ Wr2[k] + br2[k]; predictions = coarse + offsets. One warp/row.
__global__ __launch_bounds__(256)
void predictions_kernel(const float* __restrict__ R,      // (K, B*T, H)
                        const float* __restrict__ Wr2,    // (K,H,2)
                        const float* __restrict__ br2,    // (K,2)
                        const float* __restrict__ coarse, // (B,K,T,2)
                        float* __restrict__ out)          // (B,K,T,2)
{
    int wg = (blockIdx.x * blockDim.x + threadIdx.x) >> 5;
    int lane = threadIdx.x & 31;
    if (wg >= NROWS) return;
    int k = wg / ROWS_PER_MODE;
    int rem = wg % ROWS_PER_MODE;
    int b = rem / Tt, t = rem % Tt;
    const float* rrow = R + (long long)wg * Hd;
    const float* w = Wr2 + k*Hd*OUTd;
    float s0 = 0.f, s1 = 0.f;
    #pragma unroll 4
    for (int h = lane; h < Hd; h += 32){
        float rv = rrow[h];
        s0 = fmaf(rv, w[h*2+0], s0);
        s1 = fmaf(rv, w[h*2+1], s1);
    }
    #pragma unroll
    for (int o=16;o>0;o>>=1){
        s0 += __shfl_xor_sync(0xffffffffu, s0, o);
        s1 += __shfl_xor_sync(0xffffffffu, s1, o);
    }
    if (lane == 0){
        long long oidx = (((long long)b*Km + k)*Tt + t)*OUTd;
        out[oidx+0] = coarse[oidx+0] + s0 + br2[k*2+0];
        out[oidx+1] = coarse[oidx+1] + s1 + br2[k*2+1];
    }
}

// conf = c1 @ Wf2 + bf2 ; softmax over K ; write tail of d_out. One block / b.
__global__ __launch_bounds__(192)
void conf_softmax_kernel(const float* __restrict__ C1,   // (B*K,64)
                         const float* __restrict__ Wf2,  // (64,1)
                         const float* __restrict__ bf2,  // (1)
                         float* __restrict__ out)
{
    int b = blockIdx.x;
    int tid = threadIdx.x;      // 192 = 6 warps
    int k = tid >> 5, lane = tid & 31;
    __shared__ float cf[Km];
    const float* row = C1 + (b*Km + k)*64;
    float s = row[lane]*Wf2[lane] + row[32+lane]*Wf2[32+lane];
    #pragma unroll
    for (int o=16;o>0;o>>=1) s += __shfl_xor_sync(0xffffffffu, s, o);
    if (lane == 0) cf[k] = s + bf2[0];
    __syncthreads();
    if (tid < Km){
        float m = cf[0];
        #pragma unroll
        for (int i=1;i<Km;i++) m = fmaxf(m, cf[i]);
        float denom = 0.f;
        #pragma unroll
        for (int i=0;i<Km;i++) denom += expf(cf[i]-m);
        out[PRED_ELEMS + b*Km + tid] = expf(cf[tid]-m)/denom;
    }
}

// ------------------------------- launch ---------------------------------------
extern "C" void kernel_launch(void* const* d_in, const int* in_sizes, int n_in,
                              void* d_out, int out_size)
{
    const float* interaction = (const float*)d_in[0];
    const float* cooperative = (const float*)d_in[1];
    const float* map_ctx     = (const float*)d_in[2];
    const float* mode_q      = (const float*)d_in[3];
    const float* Wc1 = (const float*)d_in[4];
    const float* bc1 = (const float*)d_in[5];
    const float* Wc2 = (const float*)d_in[6];
    const float* bc2 = (const float*)d_in[7];
    const float* Wk1 = (const float*)d_in[8];
    const float* bk1 = (const float*)d_in[9];
    const float* Wk2 = (const float*)d_in[10];
    const float* bk2 = (const float*)d_in[11];
    const float* Wt  = (const float*)d_in[12];
    const float* bt  = (const float*)d_in[13];
    // Wq_a/bq_a/Wk_a/bk_a (14..17) mathematically unused (uniform attention)
    const float* Wv  = (const float*)d_in[18];
    const float* bv  = (const float*)d_in[19];
    const float* Wo  = (const float*)d_in[20];
    const float* bo  = (const float*)d_in[21];
    const float* lng = (const float*)d_in[22];
    const float* lnb = (const float*)d_in[23];
    const float* Wr1 = (const float*)d_in[24];
    const float* br1 = (const float*)d_in[25];
    const float* Wr2 = (const float*)d_in[26];
    const float* br2 = (const float*)d_in[27];
    const float* Wf1 = (const float*)d_in[28];
    const float* bf1 = (const float*)d_in[29];
    const float* Wf2 = (const float*)d_in[30];
    const float* bf2 = (const float*)d_in[31];
    float* out = (float*)d_out;

    float *comb, *tmp1, *ctx, *v, *attn, *mf, *hbuf, *coarse, *c1, *x, *r;
    cudaGetSymbolAddress((void**)&comb,   g_comb);
    cudaGetSymbolAddress((void**)&tmp1,   g_tmp1);
    cudaGetSymbolAddress((void**)&ctx,    g_context);
    cudaGetSymbolAddress((void**)&v,      g_v);
    cudaGetSymbolAddress((void**)&attn,   g_attn);
    cudaGetSymbolAddress((void**)&mf,     g_mf);
    cudaGetSymbolAddress((void**)&hbuf,   g_h);
    cudaGetSymbolAddress((void**)&coarse, g_coarse);
    cudaGetSymbolAddress((void**)&c1,     g_c1);
    cudaGetSymbolAddress((void**)&x,      g_x);
    cudaGetSymbolAddress((void**)&r,      g_r);

    // 1. combined = concat(i, c, m)
    build_combined_kernel<<<(Bsz*3*Hd + 255)/256, 256>>>(interaction, cooperative, map_ctx, comb);

    // 2. context_proj
    sgemm_kernel<ACT_GELU><<<dim3(4,4,1),256>>>(comb,0,3*Hd,  Wc1,0,Hd,  bc1,0, tmp1,0,Hd, Bsz,Hd,3*Hd);
    sgemm_kernel<ACT_NONE><<<dim3(4,4,1),256>>>(tmp1,0,Hd,    Wc2,0,Hd,  bc2,0, ctx,0,Hd,  Bsz,Hd,Hd);

    // 3. attn_out = (ctx@Wv+bv)@Wo+bo  (uniform attention collapses)
    sgemm_kernel<ACT_NONE><<<dim3(4,4,1),256>>>(ctx,0,Hd, Wv,0,Hd, bv,0, v,0,Hd,    Bsz,Hd,Hd);
    sgemm_kernel<ACT_NONE><<<dim3(4,4,1),256>>>(v,0,Hd,   Wo,0,Hd, bo,0, attn,0,Hd, Bsz,Hd,Hd);

    // 4. mode_features
    build_mf_kernel<<<(Bsz*Km*Hd + 255)/256, 256>>>(mode_q, ctx, mf);

    // 5. coarse heads (grouped over K=6)
    sgemm_kernel<ACT_GELU><<<dim3(8,4,Km),256>>>(mf, Hd, Km*Hd,
                                                 Wk1, (long long)Hd*H2, H2,
                                                 bk1, H2,
                                                 hbuf, H2, Km*H2,
                                                 Bsz, H2, Hd);
    sgemm_kernel<ACT_NONE><<<dim3(1,4,Km),256>>>(hbuf, H2, Km*H2,
                                                 Wk2, (long long)H2*TO, TO,
                                                 bk2, TO,
                                                 coarse, TO, Km*TO,
                                                 Bsz, TO, H2);

    // 6. confidence head + softmax
    sgemm_kernel<ACT_RELU><<<dim3(1,24,1),256>>>(mf,0,Hd, Wf1,0,64, bf1,0, c1,0,64, Bsz*Km,64,Hd);
    conf_softmax_kernel<<<Bsz,192>>>(c1, Wf2, bf2, out);

    // 7. fused traj_encoder + residual-add + LayerNorm -> x (K, B*T, H)
    traj_ln_kernel<<<NROWS,256>>>(coarse, attn, Wt, bt, lng, lnb, x);

    // 8. refine stage 1: r = GELU(x @ Wr1[k] + br1[k])   [dominant GEMM, 96.6 GF]
    sgemm_kernel<ACT_GELU><<<dim3(4,240,Km),256>>>(x, (long long)ROWS_PER_MODE*Hd, Hd,
                                                   Wr1, (long long)Hd*Hd, Hd,
                                                   br1, Hd,
                                                   r, (long long)ROWS_PER_MODE*Hd, Hd,
                                                   ROWS_PER_MODE, Hd, Hd);

    // 9. offsets + predictions
    predictions_kernel<<<(NROWS*32 + 255)/256, 256>>>(r, Wr2, br2, coarse, out);
}

// round 3
// speedup vs baseline: 2.5411x; 2.5411x over previous
#include <cuda_runtime.h>
#include <cuda_bf16.h>
#include <cstdint>

// Problem constants
#define Bsz 512
#define Hd  512
#define Km  6
#define Tt  60
#define OUTd 2
#define H2  1024
#define TO  120
#define ROWS_PER_MODE (Bsz*Tt)       // 30720
#define NROWS (Km*Bsz*Tt)            // 184320
#define PRED_ELEMS (Bsz*Km*Tt*OUTd)  // 368640

// refine GEMM tiling (mma.sync path)
#define CH 32                        // k elems per chunk
#define NCHUNK (Hd/CH)               // 16
#define ROWB 80                      // bytes per smem row: 32 bf16 (64B) + 16B pad
#define PLANE (128*ROWB)             // 10240 B
#define STAGE (4*PLANE)              // Ah, Al, Bh, Bl = 40960 B
#define SMEM_DYN (2*STAGE)           // 81920 B

// ---------------- scratch (device globals) ------------------------------------
__device__ float g_comb[Bsz*3*Hd];
__device__ float g_tmp1[Bsz*Hd];
__device__ float g_context[Bsz*Hd];
__device__ float g_v[Bsz*Hd];
__device__ float g_attn[Bsz*Hd];
__device__ float g_mf[Bsz*Km*Hd];
__device__ float g_h[Bsz*Km*H2];
__device__ float g_coarse[Bsz*Km*TO];
__device__ float g_c1[Bsz*Km*64];
__device__ __nv_bfloat16 g_xh[(long long)NROWS*Hd];   // LN output hi
__device__ __nv_bfloat16 g_xl[(long long)NROWS*Hd];   // LN output lo
__device__ __nv_bfloat16 g_wh[Km*Hd*Hd];              // Wr1^T hi  [k][n][kk]
__device__ __nv_bfloat16 g_wl[Km*Hd*Hd];              // Wr1^T lo
__device__ float g_part[4LL*NROWS*OUTd];              // per-ntile partial offsets

__device__ __forceinline__ float gelu_exact(float x){
    return 0.5f * x * (1.0f + erff(x * 0.7071067811865476f));
}

#define ACT_NONE 0
#define ACT_GELU 1
#define ACT_RELU 2

// ---------------- PTX helpers (base ISA only; NO tcgen05) ----------------------
__device__ __forceinline__ uint32_t smem_to_u32(const void* p) {
    uint32_t a;
    asm("{ .reg .u64 t; cvta.to.shared.u64 t, %1; cvt.u32.u64 %0, t; }" : "=r"(a) : "l"(p));
    return a;
}
__device__ __forceinline__ uint32_t lds32(uint32_t a){
    uint32_t v;
    asm volatile("ld.shared.b32 %0, [%1];" : "=r"(v) : "r"(a));
    return v;
}
#define CP_ASYNC16(dst, src) \
    asm volatile("cp.async.cg.shared.global [%0], [%1], 16;" :: "r"(dst), "l"(src))
#define CP_COMMIT() asm volatile("cp.async.commit_group;" ::: "memory")
#define CP_WAIT1() asm volatile("cp.async.wait_group 1;" ::: "memory")
#define CP_WAIT0() asm volatile("cp.async.wait_group 0;" ::: "memory")

__device__ __forceinline__ void mma16816(float* c, const uint32_t* a, uint32_t b0, uint32_t b1){
    asm volatile(
        "mma.sync.aligned.m16n8k16.row.col.f32.bf16.bf16.f32 "
        "{%0,%1,%2,%3}, {%4,%5,%6,%7}, {%8,%9}, {%0,%1,%2,%3};"
        : "+f"(c[0]), "+f"(c[1]), "+f"(c[2]), "+f"(c[3])
        : "r"(a[0]), "r"(a[1]), "r"(a[2]), "r"(a[3]), "r"(b0), "r"(b1));
}

// ---------------- FFMA SGEMM 64x64x16 tiles (small/medium GEMMs) ---------------
template<int ACT>
__global__ __launch_bounds__(256)
void sgemm64(const float* __restrict__ A, long long sAb, int lda,
             const float* __restrict__ Bm, long long sBb, int ldb,
             const float* __restrict__ bias, long long sbias,
             float* __restrict__ C, long long sCb, int ldc,
             int M, int N, int Kd)
{
    constexpr int BM=64, BN=64, BK=16;
    __shared__ float As[BK][BM];
    __shared__ float Bs[BK][BN];
    const int bz = blockIdx.z;
    A  += (long long)bz * sAb;
    Bm += (long long)bz * sBb;
    C  += (long long)bz * sCb;
    const float* bptr = bias + (long long)bz * sbias;

    const int m0 = blockIdx.y * BM;
    const int n0 = blockIdx.x * BN;
    const int tid = threadIdx.x;
    const int trow = tid >> 4, tcol = tid & 15;

    float acc[4][4];
    #pragma unroll
    for (int i=0;i<4;i++)
        #pragma unroll
        for (int j=0;j<4;j++) acc[i][j]=0.f;

    const int a_r = tid >> 2, a_c = (tid & 3) * 4;
    const int b_r = tid >> 4, b_c = (tid & 15) * 4;

    for (int k0 = 0; k0 < Kd; k0 += BK) {
        {
            int m = m0 + a_r, kk = k0 + a_c;
            if (m < M && kk + 3 < Kd) {
                float4 v = *reinterpret_cast<const float4*>(&A[(long long)m*lda + kk]);
                As[a_c+0][a_r]=v.x; As[a_c+1][a_r]=v.y; As[a_c+2][a_r]=v.z; As[a_c+3][a_r]=v.w;
            } else {
                #pragma unroll
                for (int u=0;u<4;u++)
                    As[a_c+u][a_r] = (m < M && kk+u < Kd) ? A[(long long)m*lda + kk+u] : 0.f;
            }
        }
        {
            int kk = k0 + b_r, n = n0 + b_c;
            if (kk < Kd && n + 3 < N) {
                float4 v = *reinterpret_cast<const float4*>(&Bm[(long long)kk*ldb + n]);
                Bs[b_r][b_c+0]=v.x; Bs[b_r][b_c+1]=v.y; Bs[b_r][b_c+2]=v.z; Bs[b_r][b_c+3]=v.w;
            } else {
                #pragma unroll
                for (int u=0;u<4;u++)
                    Bs[b_r][b_c+u] = (kk < Kd && n+u < N) ? Bm[(long long)kk*ldb + n+u] : 0.f;
            }
        }
        __syncthreads();
        #pragma unroll
        for (int kk=0; kk<BK; kk++){
            float4 a4 = *reinterpret_cast<const float4*>(&As[kk][trow*4]);
            float4 b4 = *reinterpret_cast<const float4*>(&Bs[kk][tcol*4]);
            float ar[4] = {a4.x,a4.y,a4.z,a4.w};
            float br[4] = {b4.x,b4.y,b4.z,b4.w};
            #pragma unroll
            for (int i=0;i<4;i++)
                #pragma unroll
                for (int j=0;j<4;j++)
                    acc[i][j] = fmaf(ar[i], br[j], acc[i][j]);
        }
        __syncthreads();
    }
    #pragma unroll
    for (int i=0;i<4;i++){
        int m = m0 + trow*4 + i;
        if (m >= M) continue;
        #pragma unroll
        for (int j=0;j<4;j++){
            int n = n0 + tcol*4 + j;
            if (n >= N) continue;
            float val = acc[i][j] + bptr[n];
            if (ACT==ACT_GELU) val = gelu_exact(val);
            else if (ACT==ACT_RELU) val = fmaxf(val, 0.f);
            C[(long long)m*ldc + n] = val;
        }
    }
}

// ---------------- elementwise helpers -----------------------------------------
__global__ void build_combined_kernel(const float* __restrict__ a,
                                      const float* __restrict__ b,
                                      const float* __restrict__ c,
                                      float* __restrict__ comb)
{
    int idx = blockIdx.x*blockDim.x + threadIdx.x;
    if (idx >= Bsz*3*Hd) return;
    int row = idx / (3*Hd), col = idx % (3*Hd);
    float v;
    if (col < Hd) v = a[row*Hd + col];
    else if (col < 2*Hd) v = b[row*Hd + col - Hd];
    else v = c[row*Hd + col - 2*Hd];
    comb[idx] = v;
}

__global__ void build_mf_kernel(const float* __restrict__ mq,
                                const float* __restrict__ ctx,
                                float* __restrict__ mf)
{
    int idx = blockIdx.x*blockDim.x + threadIdx.x;
    if (idx >= Bsz*Km*Hd) return;
    int h = idx % Hd;
    int k = (idx / Hd) % Km;
    int b = idx / (Hd*Km);
    mf[idx] = mq[k*Hd + h] + ctx[b*Hd + h];
}

// transpose + bf16-split Wr1 (K,H,H) [k][kk][n] -> [k][n][kk] hi/lo
__global__ void prep_w_kernel(const float* __restrict__ Wr1,
                              __nv_bfloat16* __restrict__ Wh,
                              __nv_bfloat16* __restrict__ Wl)
{
    long long idx = (long long)blockIdx.x*blockDim.x + threadIdx.x;
    if (idx >= (long long)Km*Hd*Hd) return;
    int kk = idx & 511;
    int n  = (idx >> 9) & 511;
    int k  = idx >> 18;
    float w = Wr1[((long long)k*Hd + kk)*Hd + n];
    __nv_bfloat16 hi = __float2bfloat16(w);
    float hif = __bfloat162float(hi);
    Wh[idx] = hi;
    Wl[idx] = __float2bfloat16(w - hif);
}

// Fused: traj = GELU(coarse@Wt + bt); u = traj + attn[b]; x = LN(u); emit bf16 split
__global__ __launch_bounds__(256)
void traj_ln_kernel(const float* __restrict__ coarse,
                    const float* __restrict__ attn,
                    const float* __restrict__ Wt,
                    const float* __restrict__ bt,
                    const float* __restrict__ ln_g,
                    const float* __restrict__ ln_b,
                    __nv_bfloat16* __restrict__ XH,
                    __nv_bfloat16* __restrict__ XL)
{
    const int row = blockIdx.x;
    const int k   = row / ROWS_PER_MODE;
    const int rem = row % ROWS_PER_MODE;
    const int b   = rem / Tt;
    const int t   = rem % Tt;
    const float c0 = coarse[((b*Km + k)*Tt + t)*OUTd + 0];
    const float c1 = coarse[((b*Km + k)*Tt + t)*OUTd + 1];
    const int tid = threadIdx.x;

    float u[2];
    float s = 0.f;
    #pragma unroll
    for (int q=0;q<2;q++){
        int h = tid + q*256;
        float pre = fmaf(c0, Wt[h], fmaf(c1, Wt[Hd + h], bt[h]));
        float uu = gelu_exact(pre) + attn[b*Hd + h];
        u[q] = uu;
        s += uu;
    }
    __shared__ float red[8];
    #pragma unroll
    for (int o=16;o>0;o>>=1) s += __shfl_xor_sync(0xffffffffu, s, o);
    if ((tid & 31) == 0) red[tid>>5] = s;
    __syncthreads();
    float mean;
    if (tid < 32) {
        float v = (tid < 8) ? red[tid] : 0.f;
        #pragma unroll
        for (int o=4;o>0;o>>=1) v += __shfl_xor_sync(0xffffffffu, v, o);
        if (tid == 0) red[0] = v * (1.f/512.f);
    }
    __syncthreads();
    mean = red[0];

    float vs = 0.f;
    #pragma unroll
    for (int q=0;q<2;q++){ float d = u[q] - mean; vs += d*d; }
    __syncthreads();
    #pragma unroll
    for (int o=16;o>0;o>>=1) vs += __shfl_xor_sync(0xffffffffu, vs, o);
    if ((tid & 31) == 0) red[tid>>5] = vs;
    __syncthreads();
    if (tid < 32) {
        float v = (tid < 8) ? red[tid] : 0.f;
        #pragma unroll
        for (int o=4;o>0;o>>=1) v += __shfl_xor_sync(0xffffffffu, v, o);
        if (tid == 0) red[0] = rsqrtf(v * (1.f/512.f) + 1e-5f);
    }
    __syncthreads();
    float rstd = red[0];

    long long rbase = (long long)row * Hd;
    #pragma unroll
    for (int q=0;q<2;q++){
        int h = tid + q*256;
        float xv = (u[q] - mean) * rstd * ln_g[h] + ln_b[h];
        __nv_bfloat16 hb = __float2bfloat16(xv);
        float hif = __bfloat162float(hb);
        XH[rbase + h] = hb;
        XL[rbase + h] = __float2bfloat16(xv - hif);
    }
}

// ---------------- refine GEMM via mma.sync + fused epilogue --------------------
// grid (nt=4, mtile=240, mode=6), 128 threads (4 warps: 2(m) x 2(n), warp 64x64)
// pre = x @ Wr1[k] (bf16 3-term split, single pass), r = GELU(pre + br1),
// P[nt][row][o] = sum over this CTA's 128 n of r * Wr2[k][n][o]
__global__ __launch_bounds__(128)
void refine_mma_kernel(const __nv_bfloat16* __restrict__ XH,
                       const __nv_bfloat16* __restrict__ XL,
                       const __nv_bfloat16* __restrict__ WH,
                       const __nv_bfloat16* __restrict__ WL,
                       const float* __restrict__ br1,
                       const float* __restrict__ Wr2,
                       float* __restrict__ P)
{
    extern __shared__ char smem[];
    const uint32_t sbase = smem_to_u32(smem);
    const int tid  = threadIdx.x;
    const int wid  = tid >> 5;
    const int lane = tid & 31;
    const int wm   = wid & 1;       // m half (64 rows)
    const int wn   = wid >> 1;      // n half (64 cols)
    const int nt   = blockIdx.x;    // 0..3
    const int m0   = blockIdx.y * 128;
    const int mode = blockIdx.z;

    const __nv_bfloat16* xh = XH + ((long long)mode * ROWS_PER_MODE + m0) * Hd;
    const __nv_bfloat16* xl = XL + ((long long)mode * ROWS_PER_MODE + m0) * Hd;
    const __nv_bfloat16* wh = WH + ((long long)mode * Hd + nt * 128) * Hd;
    const __nv_bfloat16* wl = WL + ((long long)mode * Hd + nt * 128) * Hd;

    float acc[4][8][4];
    #pragma unroll
    for (int i=0;i<4;i++)
        #pragma unroll
        for (int j=0;j<8;j++)
            #pragma unroll
            for (int q=0;q<4;q++) acc[i][j][q]=0.f;

    // chunk loader: planes {xh, xl, wh, wl}, 16B cp.async each
    const int lr = tid >> 2;       // 0..31 (row sub-index)
    const int lq = tid & 3;        // 16B quad within 64B row
    auto load_chunk = [&](int c, int stage){
        uint32_t sb = sbase + stage * STAGE;
        #pragma unroll
        for (int kk = 0; kk < 16; kk++) {
            const int plane = kk >> 2;
            const int r = (kk & 3) * 32 + lr;
            const __nv_bfloat16* src =
                (plane==0) ? xh : (plane==1) ? xl : (plane==2) ? wh : wl;
            uint32_t dst = sb + plane*PLANE + r*ROWB + lq*16;
            const char* gsrc = (const char*)src + ((long long)r*Hd + c*CH + lq*8)*2;
            CP_ASYNC16(dst, gsrc);
        }
    };

    load_chunk(0, 0);
    CP_COMMIT();

    int buf = 0;
    #pragma unroll 1
    for (int c = 0; c < NCHUNK; c++) {
        if (c + 1 < NCHUNK) { load_chunk(c + 1, buf ^ 1); CP_COMMIT(); CP_WAIT1(); }
        else                { CP_WAIT0(); }
        __syncthreads();

        const uint32_t sb = sbase + buf * STAGE;
        #pragma unroll
        for (int ks = 0; ks < 2; ks++) {
            // A fragments (hi & lo)
            uint32_t ah[4][4], al[4][4];
            const uint32_t abase = sb + (wm*64 + (lane>>2))*ROWB + ks*32 + (lane&3)*4;
            #pragma unroll
            for (int i=0;i<4;i++){
                uint32_t a = abase + i*16*ROWB;
                ah[i][0] = lds32(a);
                ah[i][1] = lds32(a + 8*ROWB);
                ah[i][2] = lds32(a + 16);
                ah[i][3] = lds32(a + 8*ROWB + 16);
                al[i][0] = lds32(a + PLANE);
                al[i][1] = lds32(a + PLANE + 8*ROWB);
                al[i][2] = lds32(a + PLANE + 16);
                al[i][3] = lds32(a + PLANE + 8*ROWB + 16);
            }
            const uint32_t bbase = sb + 2*PLANE + (wn*64 + (lane>>2))*ROWB + ks*32 + (lane&3)*4;
            #pragma unroll
            for (int j=0;j<8;j++){
                uint32_t b = bbase + j*8*ROWB;
                uint32_t bh0 = lds32(b);
                uint32_t bh1 = lds32(b + 16);
                uint32_t bl0 = lds32(b + PLANE);
                uint32_t bl1 = lds32(b + PLANE + 16);
                #pragma unroll
                for (int i=0;i<4;i++){
                    mma16816(acc[i][j], ah[i], bh0, bh1);   // xh*wh
                    mma16816(acc[i][j], al[i], bh0, bh1);   // xl*wh
                    mma16816(acc[i][j], ah[i], bl0, bl1);   // xh*wl
                }
            }
        }
        __syncthreads();
        buf ^= 1;
    }

    // ---- epilogue: GELU(pre + br1) dot Wr2 over this CTA's 128 n-cols ----
    const float* br1m = br1 + mode * Hd;
    const float* wr2m = Wr2 + mode * Hd * OUTd;
    const int nloc0 = nt*128 + wn*64;

    float p0[4][2], p1[4][2];
    #pragma unroll
    for (int i=0;i<4;i++)
        #pragma unroll
        for (int h2=0;h2<2;h2++){ p0[i][h2]=0.f; p1[i][h2]=0.f; }

    #pragma unroll
    for (int j=0;j<8;j++){
        #pragma unroll
        for (int nn=0;nn<2;nn++){
            const int n = nloc0 + j*8 + (lane&3)*2 + nn;
            const float bv = br1m[n];
            const float w0 = wr2m[n*2+0];
            const float w1 = wr2m[n*2+1];
            #pragma unroll
            for (int i=0;i<4;i++){
                #pragma unroll
                for (int h2=0;h2<2;h2++){
                    float r = gelu_exact(acc[i][j][h2*2+nn] + bv);
                    p0[i][h2] = fmaf(r, w0, p0[i][h2]);
                    p1[i][h2] = fmaf(r, w1, p1[i][h2]);
                }
            }
        }
    }
    // quad reduce (lanes sharing the same rows)
    #pragma unroll
    for (int i=0;i<4;i++)
        #pragma unroll
        for (int h2=0;h2<2;h2++){
            #pragma unroll
            for (int o=1;o<4;o<<=1){
                p0[i][h2] += __shfl_xor_sync(0xffffffffu, p0[i][h2], o);
                p1[i][h2] += __shfl_xor_sync(0xffffffffu, p1[i][h2], o);
            }
        }

    __syncthreads();                     // smem reuse as reduction scratch
    float* red0 = reinterpret_cast<float*>(smem);
    float* red1 = red0 + 128;
    if (wn == 0 && (lane & 3) == 0){
        #pragma unroll
        for (int i=0;i<4;i++)
            #pragma unroll
            for (int h2=0;h2<2;h2++){
                int rl = wm*64 + i*16 + h2*8 + (lane>>2);
                red0[rl] = p0[i][h2];
                red1[rl] = p1[i][h2];
            }
    }
    __syncthreads();
    if (wn == 1 && (lane & 3) == 0){
        #pragma unroll
        for (int i=0;i<4;i++)
            #pragma unroll
            for (int h2=0;h2<2;h2++){
                int rl = wm*64 + i*16 + h2*8 + (lane>>2);
                long long grow = (long long)mode * ROWS_PER_MODE + m0 + rl;
                long long pidx = ((long long)nt * NROWS + grow) * 2;
                P[pidx + 0] = p0[i][h2] + red0[rl];
                P[pidx + 1] = p1[i][h2] + red1[rl];
            }
    }
}

// predictions = coarse + br2 + sum of 4 ntile partials
__global__ void finalize_kernel(const float* __restrict__ coarse,
                                const float* __restrict__ br2,
                                const float* __restrict__ P,
                                float* __restrict__ out)
{
    int idx = blockIdx.x*blockDim.x + threadIdx.x;
    if (idx >= PRED_ELEMS) return;
    int o = idx & 1;
    int t = (idx >> 1) % Tt;
    int k = ((idx >> 1) / Tt) % Km;
    int b = idx / (2*Tt*Km);
    long long grow = (long long)k * ROWS_PER_MODE + b * Tt + t;
    float s = coarse[idx] + br2[k*2+o];
    #pragma unroll
    for (int nt=0; nt<4; nt++)
        s += P[((long long)nt * NROWS + grow)*2 + o];
    out[idx] = s;
}

// conf head epilogue + softmax
__global__ __launch_bounds__(192)
void conf_softmax_kernel(const float* __restrict__ C1,
                         const float* __restrict__ Wf2,
                         const float* __restrict__ bf2,
                         float* __restrict__ out)
{
    int b = blockIdx.x;
    int tid = threadIdx.x;
    int k = tid >> 5, lane = tid & 31;
    __shared__ float cf[Km];
    const float* row = C1 + (b*Km + k)*64;
    float s = row[lane]*Wf2[lane] + row[32+lane]*Wf2[32+lane];
    #pragma unroll
    for (int o=16;o>0;o>>=1) s += __shfl_xor_sync(0xffffffffu, s, o);
    if (lane == 0) cf[k] = s + bf2[0];
    __syncthreads();
    if (tid < Km){
        float m = cf[0];
        #pragma unroll
        for (int i=1;i<Km;i++) m = fmaxf(m, cf[i]);
        float denom = 0.f;
        #pragma unroll
        for (int i=0;i<Km;i++) denom += expf(cf[i]-m);
        out[PRED_ELEMS + b*Km + tid] = expf(cf[tid]-m)/denom;
    }
}

// ------------------------------- launch ---------------------------------------
extern "C" void kernel_launch(void* const* d_in, const int* in_sizes, int n_in,
                              void* d_out, int out_size)
{
    const float* interaction = (const float*)d_in[0];
    const float* cooperative = (const float*)d_in[1];
    const float* map_ctx     = (const float*)d_in[2];
    const float* mode_q      = (const float*)d_in[3];
    const float* Wc1 = (const float*)d_in[4];
    const float* bc1 = (const float*)d_in[5];
    const float* Wc2 = (const float*)d_in[6];
    const float* bc2 = (const float*)d_in[7];
    const float* Wk1 = (const float*)d_in[8];
    const float* bk1 = (const float*)d_in[9];
    const float* Wk2 = (const float*)d_in[10];
    const float* bk2 = (const float*)d_in[11];
    const float* Wt  = (const float*)d_in[12];
    const float* bt  = (const float*)d_in[13];
    const float* Wv  = (const float*)d_in[18];
    const float* bv  = (const float*)d_in[19];
    const float* Wo  = (const float*)d_in[20];
    const float* bo  = (const float*)d_in[21];
    const float* lng = (const float*)d_in[22];
    const float* lnb = (const float*)d_in[23];
    const float* Wr1 = (const float*)d_in[24];
    const float* br1 = (const float*)d_in[25];
    const float* Wr2 = (const float*)d_in[26];
    const float* br2 = (const float*)d_in[27];
    const float* Wf1 = (const float*)d_in[28];
    const float* bf1 = (const float*)d_in[29];
    const float* Wf2 = (const float*)d_in[30];
    const float* bf2 = (const float*)d_in[31];
    float* out = (float*)d_out;

    float *comb, *tmp1, *ctx, *v, *attn, *mf, *hbuf, *coarse, *c1, *part;
    __nv_bfloat16 *xh, *xl, *wgh, *wgl;
    cudaGetSymbolAddress((void**)&comb,   g_comb);
    cudaGetSymbolAddress((void**)&tmp1,   g_tmp1);
    cudaGetSymbolAddress((void**)&ctx,    g_context);
    cudaGetSymbolAddress((void**)&v,      g_v);
    cudaGetSymbolAddress((void**)&attn,   g_attn);
    cudaGetSymbolAddress((void**)&mf,     g_mf);
    cudaGetSymbolAddress((void**)&hbuf,   g_h);
    cudaGetSymbolAddress((void**)&coarse, g_coarse);
    cudaGetSymbolAddress((void**)&c1,     g_c1);
    cudaGetSymbolAddress((void**)&part,   g_part);
    cudaGetSymbolAddress((void**)&xh,     g_xh);
    cudaGetSymbolAddress((void**)&xl,     g_xl);
    cudaGetSymbolAddress((void**)&wgh,    g_wh);
    cudaGetSymbolAddress((void**)&wgl,    g_wl);

    cudaFuncSetAttribute(refine_mma_kernel,
                         cudaFuncAttributeMaxDynamicSharedMemorySize, SMEM_DYN);

    // weight prep for refine GEMM (independent of the main chain)
    prep_w_kernel<<<(Km*Hd*Hd + 255)/256, 256>>>(Wr1, wgh, wgl);

    // 1. combined
    build_combined_kernel<<<(Bsz*3*Hd + 255)/256, 256>>>(interaction, cooperative, map_ctx, comb);

    // 2. context_proj
    sgemm64<ACT_GELU><<<dim3(8,8,1),256>>>(comb,0,3*Hd,  Wc1,0,Hd,  bc1,0, tmp1,0,Hd, Bsz,Hd,3*Hd);
    sgemm64<ACT_NONE><<<dim3(8,8,1),256>>>(tmp1,0,Hd,    Wc2,0,Hd,  bc2,0, ctx,0,Hd,  Bsz,Hd,Hd);

    // 3. attn_out = (ctx@Wv+bv)@Wo+bo   (uniform attention collapses)
    sgemm64<ACT_NONE><<<dim3(8,8,1),256>>>(ctx,0,Hd, Wv,0,Hd, bv,0, v,0,Hd,    Bsz,Hd,Hd);
    sgemm64<ACT_NONE><<<dim3(8,8,1),256>>>(v,0,Hd,   Wo,0,Hd, bo,0, attn,0,Hd, Bsz,Hd,Hd);

    // 4. mode_features
    build_mf_kernel<<<(Bsz*Km*Hd + 255)/256, 256>>>(mode_q, ctx, mf);

    // 5. coarse heads (grouped over K=6)
    sgemm64<ACT_GELU><<<dim3(16,8,Km),256>>>(mf, Hd, Km*Hd,
                                             Wk1, (long long)Hd*H2, H2,
                                             bk1, H2,
                                             hbuf, H2, Km*H2,
                                             Bsz, H2, Hd);
    sgemm64<ACT_NONE><<<dim3(2,8,Km),256>>>(hbuf, H2, Km*H2,
                                            Wk2, (long long)H2*TO, TO,
                                            bk2, TO,
                                            coarse, TO, Km*TO,
                                            Bsz, TO, H2);

    // 6. confidence
    sgemm64<ACT_RELU><<<dim3(1,48,1),256>>>(mf,0,Hd, Wf1,0,64, bf1,0, c1,0,64, Bsz*Km,64,Hd);
    conf_softmax_kernel<<<Bsz,192>>>(c1, Wf2, bf2, out);

    // 7. fused traj + residual + LN -> bf16 split
    traj_ln_kernel<<<NROWS,256>>>(coarse, attn, Wt, bt, lng, lnb, xh, xl);

    // 8. refine GEMM (mma.sync bf16 3-term) + fused GELU + Wr2 partial reduction
    refine_mma_kernel<<<dim3(4,240,Km),128, SMEM_DYN>>>(
        xh, xl, wgh, wgl, br1, Wr2, part);

    // 9. predictions
    finalize_kernel<<<(PRED_ELEMS + 255)/256, 256>>>(coarse, br2, part, out);
}

// round 4
// speedup vs baseline: 2.9527x; 1.1620x over previous
#include <cuda_runtime.h>
#include <cuda_fp16.h>
#include <cstdint>

// Problem constants
#define Bsz 512
#define Hd  512
#define Km  6
#define Tt  60
#define OUTd 2
#define H2  1024
#define TO  120
#define ROWS_PER_MODE (Bsz*Tt)       // 30720
#define NROWS (Km*Bsz*Tt)            // 184320
#define PRED_ELEMS (Bsz*Km*Tt*OUTd)  // 368640

// refine GEMM tiling
#define CH 32                        // k elems per chunk
#define NCHUNK (Hd/CH)               // 16
#define ROWB 80                      // 32 fp16 (64B) + 16B pad
#define PLANE (128*ROWB)             // 10240 B
#define STAGE (3*PLANE)              // Ah, Al, B = 30720 B
#define SMEM_DYN (2*STAGE)           // 61440 B

// ---------------- scratch (device globals) ------------------------------------
__device__ float g_tmp1[Bsz*Hd];
__device__ float g_context[Bsz*Hd];
__device__ float g_attn[Bsz*Hd];
__device__ float g_h[Bsz*Km*H2];
__device__ float g_coarse[Bsz*Km*TO];
__device__ float g_c1[Bsz*Km*64];
__device__ float g_wvo[Hd*Hd];
__device__ float g_bvo[Hd];
__device__ float g_zero512[Hd];                       // stays zero
__device__ __half g_xh[(long long)NROWS*Hd];          // LN output hi (fp16)
__device__ __half g_xl[(long long)NROWS*Hd];          // LN output lo (fp16)
__device__ __half g_w16[(long long)Km*Hd*Hd];         // Wr1^T fp16 [k][n][kk]
__device__ float g_part[4LL*NROWS*OUTd];              // per-ntile partials

__device__ __forceinline__ float gelu_exact(float x){
    return 0.5f * x * (1.0f + erff(x * 0.7071067811865476f));
}

#define ACT_NONE 0
#define ACT_GELU 1
#define ACT_RELU 2

// A-source modes for sgemm64
#define AM_PLAIN  0
#define AM_CONCAT 1
#define AM_CTXQ   2   // A[m][k] = ctx[m][k] + mq[bz][k]
#define AM_CONF   3   // A[m][k] = ctx[m/Km][k] + mq[m%Km][k]

// ---------------- PTX helpers ---------------------------------------------------
__device__ __forceinline__ uint32_t smem_to_u32(const void* p) {
    uint32_t a;
    asm("{ .reg .u64 t; cvta.to.shared.u64 t, %1; cvt.u32.u64 %0, t; }" : "=r"(a) : "l"(p));
    return a;
}
__device__ __forceinline__ uint32_t lds32(uint32_t a){
    uint32_t v;
    asm volatile("ld.shared.b32 %0, [%1];" : "=r"(v) : "r"(a));
    return v;
}
#define CP_ASYNC16(dst, src) \
    asm volatile("cp.async.cg.shared.global [%0], [%1], 16;" :: "r"(dst), "l"(src))
#define CP_COMMIT() asm volatile("cp.async.commit_group;" ::: "memory")
#define CP_WAIT1() asm volatile("cp.async.wait_group 1;" ::: "memory")
#define CP_WAIT0() asm volatile("cp.async.wait_group 0;" ::: "memory")

__device__ __forceinline__ void mma16816(float* c, const uint32_t* a, uint32_t b0, uint32_t b1){
    asm volatile(
        "mma.sync.aligned.m16n8k16.row.col.f32.f16.f16.f32 "
        "{%0,%1,%2,%3}, {%4,%5,%6,%7}, {%8,%9}, {%0,%1,%2,%3};"
        : "+f"(c[0]), "+f"(c[1]), "+f"(c[2]), "+f"(c[3])
        : "r"(a[0]), "r"(a[1]), "r"(a[2]), "r"(a[3]), "r"(b0), "r"(b1));
}

// ---------------- FFMA SGEMM 64x64x16, register-prefetch double buffer ---------
// Assumes M % 64 == 0 and Kd % 16 == 0 (true for all call sites). N guarded.
template<int ACT, int AMODE>
__global__ __launch_bounds__(256)
void sgemm64(const float* __restrict__ A, const float* __restrict__ A1,
             const float* __restrict__ A2,
             long long sAb, int lda,
             const float* __restrict__ Bm, long long sBb, int ldb,
             const float* __restrict__ bias, long long sbias,
             float* __restrict__ C, long long sCb, int ldc,
             int M, int N, int Kd)
{
    constexpr int BM=64, BN=64, BK=16;
    __shared__ float As[BK][BM];
    __shared__ float Bs[BK][BN];
    const int bz = blockIdx.z;
    Bm += (long long)bz * sBb;
    C  += (long long)bz * sCb;
    const float* bptr = bias + (long long)bz * sbias;

    const int m0 = blockIdx.y * BM;
    const int n0 = blockIdx.x * BN;
    const int tid = threadIdx.x;
    const int trow = tid >> 4, tcol = tid & 15;
    const int a_r = tid >> 2, a_c = (tid & 3) * 4;    // 64 rows x 4 quads
    const int b_r = tid >> 4, b_c = (tid & 15) * 4;   // 16 rows x 16 quads

    auto loadA4 = [&](int m, int kk)->float4 {
        if (AMODE == AM_PLAIN)
            return *reinterpret_cast<const float4*>(&A[bz*sAb + (long long)m*lda + kk]);
        if (AMODE == AM_CONCAT) {
            const float* p = (kk < 512) ? A : (kk < 1024) ? A1 : A2;
            return *reinterpret_cast<const float4*>(&p[(long long)m*512 + (kk & 511)]);
        }
        if (AMODE == AM_CTXQ) {
            float4 u = *reinterpret_cast<const float4*>(&A [(long long)m*512 + kk]);
            float4 v = *reinterpret_cast<const float4*>(&A1[(long long)bz*512 + kk]);
            return make_float4(u.x+v.x, u.y+v.y, u.z+v.z, u.w+v.w);
        }
        // AM_CONF
        int b = m / Km, km = m - b * Km;
        float4 u = *reinterpret_cast<const float4*>(&A [(long long)b*512 + kk]);
        float4 v = *reinterpret_cast<const float4*>(&A1[(long long)km*512 + kk]);
        return make_float4(u.x+v.x, u.y+v.y, u.z+v.z, u.w+v.w);
    };
    auto loadB4 = [&](int kk, int n)->float4 {
        if (n + 3 < N)
            return *reinterpret_cast<const float4*>(&Bm[(long long)kk*ldb + n]);
        float4 r; 
        r.x = (n+0 < N) ? Bm[(long long)kk*ldb + n+0] : 0.f;
        r.y = (n+1 < N) ? Bm[(long long)kk*ldb + n+1] : 0.f;
        r.z = (n+2 < N) ? Bm[(long long)kk*ldb + n+2] : 0.f;
        r.w = (n+3 < N) ? Bm[(long long)kk*ldb + n+3] : 0.f;
        return r;
    };

    float acc[4][4];
    #pragma unroll
    for (int i=0;i<4;i++)
        #pragma unroll
        for (int j=0;j<4;j++) acc[i][j]=0.f;

    float4 pa = loadA4(m0 + a_r, a_c);
    float4 pb = loadB4(b_r, n0 + b_c);

    for (int k0 = 0; k0 < Kd; k0 += BK) {
        As[a_c+0][a_r]=pa.x; As[a_c+1][a_r]=pa.y; As[a_c+2][a_r]=pa.z; As[a_c+3][a_r]=pa.w;
        Bs[b_r][b_c+0]=pb.x; Bs[b_r][b_c+1]=pb.y; Bs[b_r][b_c+2]=pb.z; Bs[b_r][b_c+3]=pb.w;
        __syncthreads();
        if (k0 + BK < Kd) {
            pa = loadA4(m0 + a_r, k0 + BK + a_c);
            pb = loadB4(k0 + BK + b_r, n0 + b_c);
        }
        #pragma unroll
        for (int kk=0; kk<BK; kk++){
            float4 a4 = *reinterpret_cast<const float4*>(&As[kk][trow*4]);
            float4 b4 = *reinterpret_cast<const float4*>(&Bs[kk][tcol*4]);
            float ar[4] = {a4.x,a4.y,a4.z,a4.w};
            float br[4] = {b4.x,b4.y,b4.z,b4.w};
            #pragma unroll
            for (int i=0;i<4;i++)
                #pragma unroll
                for (int j=0;j<4;j++)
                    acc[i][j] = fmaf(ar[i], br[j], acc[i][j]);
        }
        __syncthreads();
    }
    #pragma unroll
    for (int i=0;i<4;i++){
        int m = m0 + trow*4 + i;
        #pragma unroll
        for (int j=0;j<4;j++){
            int n = n0 + tcol*4 + j;
            if (n >= N) continue;
            float val = acc[i][j] + bptr[n];
            if (ACT==ACT_GELU) val = gelu_exact(val);
            else if (ACT==ACT_RELU) val = fmaxf(val, 0.f);
            C[(long long)m*ldc + n] = val;
        }
    }
}

// ---------------- small prep kernels --------------------------------------------
// bvo = bv @ Wo + bo
__global__ void bvo_kernel(const float* __restrict__ bv, const float* __restrict__ Wo,
                           const float* __restrict__ bo, float* __restrict__ bvo)
{
    int n = blockIdx.x*blockDim.x + threadIdx.x;
    if (n >= Hd) return;
    float s = bo[n];
    for (int k = 0; k < Hd; k++) s = fmaf(bv[k], Wo[k*Hd + n], s);
    bvo[n] = s;
}

// transpose Wr1 (K,H,H) [k][kk][n] -> fp16 [k][n][kk]
__global__ void prep_w_kernel(const float* __restrict__ Wr1, __half* __restrict__ W16)
{
    long long idx = (long long)blockIdx.x*blockDim.x + threadIdx.x;
    if (idx >= (long long)Km*Hd*Hd) return;
    int kk = idx & 511;
    int n  = (idx >> 9) & 511;
    int k  = idx >> 18;
    W16[idx] = __float2half_rn(Wr1[((long long)k*Hd + kk)*Hd + n]);
}

// Fused: traj = GELU(coarse@Wt + bt); u = traj + attn[b]; x = LN(u); emit fp16 hi/lo
__global__ __launch_bounds__(256)
void traj_ln_kernel(const float* __restrict__ coarse,
                    const float* __restrict__ attn,
                    const float* __restrict__ Wt,
                    const float* __restrict__ bt,
                    const float* __restrict__ ln_g,
                    const float* __restrict__ ln_b,
                    __half* __restrict__ XH,
                    __half* __restrict__ XL)
{
    const int row = blockIdx.x;
    const int k   = row / ROWS_PER_MODE;
    const int rem = row % ROWS_PER_MODE;
    const int b   = rem / Tt;
    const int t   = rem % Tt;
    const float c0 = coarse[((b*Km + k)*Tt + t)*OUTd + 0];
    const float c1 = coarse[((b*Km + k)*Tt + t)*OUTd + 1];
    const int tid = threadIdx.x;

    float u[2];
    float s = 0.f;
    #pragma unroll
    for (int q=0;q<2;q++){
        int h = tid + q*256;
        float pre = fmaf(c0, Wt[h], fmaf(c1, Wt[Hd + h], bt[h]));
        float uu = gelu_exact(pre) + attn[b*Hd + h];
        u[q] = uu;
        s += uu;
    }
    __shared__ float red[8];
    #pragma unroll
    for (int o=16;o>0;o>>=1) s += __shfl_xor_sync(0xffffffffu, s, o);
    if ((tid & 31) == 0) red[tid>>5] = s;
    __syncthreads();
    float mean;
    if (tid < 32) {
        float v = (tid < 8) ? red[tid] : 0.f;
        #pragma unroll
        for (int o=4;o>0;o>>=1) v += __shfl_xor_sync(0xffffffffu, v, o);
        if (tid == 0) red[0] = v * (1.f/512.f);
    }
    __syncthreads();
    mean = red[0];

    float vs = 0.f;
    #pragma unroll
    for (int q=0;q<2;q++){ float d = u[q] - mean; vs += d*d; }
    __syncthreads();
    #pragma unroll
    for (int o=16;o>0;o>>=1) vs += __shfl_xor_sync(0xffffffffu, vs, o);
    if ((tid & 31) == 0) red[tid>>5] = vs;
    __syncthreads();
    if (tid < 32) {
        float v = (tid < 8) ? red[tid] : 0.f;
        #pragma unroll
        for (int o=4;o>0;o>>=1) v += __shfl_xor_sync(0xffffffffu, v, o);
        if (tid == 0) red[0] = rsqrtf(v * (1.f/512.f) + 1e-5f);
    }
    __syncthreads();
    float rstd = red[0];

    long long rbase = (long long)row * Hd;
    #pragma unroll
    for (int q=0;q<2;q++){
        int h = tid + q*256;
        float xv = (u[q] - mean) * rstd * ln_g[h] + ln_b[h];
        __half hb = __float2half_rn(xv);
        XH[rbase + h] = hb;
        XL[rbase + h] = __float2half_rn(xv - __half2float(hb));
    }
}

// ---------------- refine GEMM (mma.sync fp16 2-term) + fused epilogue ----------
// grid (nt=4, mtile=240, mode=6), 256 threads = 8 warps (4 m x 2 n), warp 32x64
__global__ __launch_bounds__(256)
void refine_mma_kernel(const __half* __restrict__ XH,
                       const __half* __restrict__ XL,
                       const __half* __restrict__ W16,
                       const float* __restrict__ br1,
                       const float* __restrict__ Wr2,
                       float* __restrict__ P)
{
    extern __shared__ char smem[];
    const uint32_t sbase = smem_to_u32(smem);
    const int tid  = threadIdx.x;
    const int wid  = tid >> 5;
    const int lane = tid & 31;
    const int wm   = wid & 3;       // m quarter (32 rows)
    const int wn   = wid >> 2;      // n half (64 cols)
    const int nt   = blockIdx.x;    // 0..3
    const int m0   = blockIdx.y * 128;
    const int mode = blockIdx.z;

    const __half* xh = XH  + ((long long)mode * ROWS_PER_MODE + m0) * Hd;
    const __half* xl = XL  + ((long long)mode * ROWS_PER_MODE + m0) * Hd;
    const __half* wv = W16 + ((long long)mode * Hd + nt * 128) * Hd;

    float acc[2][8][4];
    #pragma unroll
    for (int i=0;i<2;i++)
        #pragma unroll
        for (int j=0;j<8;j++)
            #pragma unroll
            for (int q=0;q<4;q++) acc[i][j][q]=0.f;

    // loader: 3 planes x 128 rows x 64B; thread: row=tid>>1, 32B half-row
    const int lr = tid >> 1;
    const int lh = (tid & 1) * 32;
    auto load_chunk = [&](int c, int stage){
        uint32_t sb = sbase + stage * STAGE;
        const __half* srcs[3] = {xh, xl, wv};
        #pragma unroll
        for (int p = 0; p < 3; p++) {
            uint32_t dst = sb + p*PLANE + lr*ROWB + lh;
            const char* g = (const char*)srcs[p] + ((long long)lr*Hd + c*CH)*2 + lh;
            CP_ASYNC16(dst, g);
            CP_ASYNC16(dst + 16, g + 16);
        }
    };

    load_chunk(0, 0);
    CP_COMMIT();

    int buf = 0;
    #pragma unroll 1
    for (int c = 0; c < NCHUNK; c++) {
        if (c + 1 < NCHUNK) { load_chunk(c + 1, buf ^ 1); CP_COMMIT(); CP_WAIT1(); }
        else                { CP_WAIT0(); }
        __syncthreads();

        const uint32_t sb = sbase + buf * STAGE;
        #pragma unroll
        for (int ks = 0; ks < 2; ks++) {
            uint32_t ah[2][4], al[2][4];
            const uint32_t abase = sb + (wm*32 + (lane>>2))*ROWB + ks*32 + (lane&3)*4;
            #pragma unroll
            for (int i=0;i<2;i++){
                uint32_t a = abase + i*16*ROWB;
                ah[i][0] = lds32(a);
                ah[i][1] = lds32(a + 8*ROWB);
                ah[i][2] = lds32(a + 16);
                ah[i][3] = lds32(a + 8*ROWB + 16);
                al[i][0] = lds32(a + PLANE);
                al[i][1] = lds32(a + PLANE + 8*ROWB);
                al[i][2] = lds32(a + PLANE + 16);
                al[i][3] = lds32(a + PLANE + 8*ROWB + 16);
            }
            const uint32_t bbase = sb + 2*PLANE + (wn*64 + (lane>>2))*ROWB + ks*32 + (lane&3)*4;
            #pragma unroll
            for (int j=0;j<8;j++){
                uint32_t b = bbase + j*8*ROWB;
                uint32_t b0 = lds32(b);
                uint32_t b1 = lds32(b + 16);
                #pragma unroll
                for (int i=0;i<2;i++){
                    mma16816(acc[i][j], ah[i], b0, b1);   // xh*wh
                    mma16816(acc[i][j], al[i], b0, b1);   // xl*wh
                }
            }
        }
        __syncthreads();
        buf ^= 1;
    }

    // ---- epilogue: GELU(pre + br1) dot Wr2 over this CTA's 128 n-cols ----
    const float* br1m = br1 + mode * Hd;
    const float* wr2m = Wr2 + mode * Hd * OUTd;
    const int nloc0 = nt*128 + wn*64;

    float p0[2][2], p1[2][2];
    #pragma unroll
    for (int i=0;i<2;i++)
        #pragma unroll
        for (int h2=0;h2<2;h2++){ p0[i][h2]=0.f; p1[i][h2]=0.f; }

    #pragma unroll
    for (int j=0;j<8;j++){
        #pragma unroll
        for (int nn=0;nn<2;nn++){
            const int n = nloc0 + j*8 + (lane&3)*2 + nn;
            const float bv = br1m[n];
            const float w0 = wr2m[n*2+0];
            const float w1 = wr2m[n*2+1];
            #pragma unroll
            for (int i=0;i<2;i++){
                #pragma unroll
                for (int h2=0;h2<2;h2++){
                    float r = gelu_exact(acc[i][j][h2*2+nn] + bv);
                    p0[i][h2] = fmaf(r, w0, p0[i][h2]);
                    p1[i][h2] = fmaf(r, w1, p1[i][h2]);
                }
            }
        }
    }
    // quad reduce (lanes sharing the same rows)
    #pragma unroll
    for (int i=0;i<2;i++)
        #pragma unroll
        for (int h2=0;h2<2;h2++){
            #pragma unroll
            for (int o=1;o<4;o<<=1){
                p0[i][h2] += __shfl_xor_sync(0xffffffffu, p0[i][h2], o);
                p1[i][h2] += __shfl_xor_sync(0xffffffffu, p1[i][h2], o);
            }
        }

    __syncthreads();
    float* red0 = reinterpret_cast<float*>(smem);
    float* red1 = red0 + 128;
    if (wn == 0 && (lane & 3) == 0){
        #pragma unroll
        for (int i=0;i<2;i++)
            #pragma unroll
            for (int h2=0;h2<2;h2++){
                int rl = wm*32 + i*16 + h2*8 + (lane>>2);
                red0[rl] = p0[i][h2];
                red1[rl] = p1[i][h2];
            }
    }
    __syncthreads();
    if (wn == 1 && (lane & 3) == 0){
        #pragma unroll
        for (int i=0;i<2;i++)
            #pragma unroll
            for (int h2=0;h2<2;h2++){
                int rl = wm*32 + i*16 + h2*8 + (lane>>2);
                long long grow = (long long)mode * ROWS_PER_MODE + m0 + rl;
                long long pidx = ((long long)nt * NROWS + grow) * 2;
                P[pidx + 0] = p0[i][h2] + red0[rl];
                P[pidx + 1] = p1[i][h2] + red1[rl];
            }
    }
}

// predictions = coarse + br2 + sum of 4 ntile partials
__global__ void finalize_kernel(const float* __restrict__ coarse,
                                const float* __restrict__ br2,
                                const float* __restrict__ P,
                                float* __restrict__ out)
{
    int idx = blockIdx.x*blockDim.x + threadIdx.x;
    if (idx >= PRED_ELEMS) return;
    int o = idx & 1;
    int t = (idx >> 1) % Tt;
    int k = ((idx >> 1) / Tt) % Km;
    int b = idx / (2*Tt*Km);
    long long grow = (long long)k * ROWS_PER_MODE + b * Tt + t;
    float s = coarse[idx] + br2[k*2+o];
    #pragma unroll
    for (int nt=0; nt<4; nt++)
        s += P[((long long)nt * NROWS + grow)*2 + o];
    out[idx] = s;
}

// conf head epilogue + softmax
__global__ __launch_bounds__(192)
void conf_softmax_kernel(const float* __restrict__ C1,
                         const float* __restrict__ Wf2,
                         const float* __restrict__ bf2,
                         float* __restrict__ out)
{
    int b = blockIdx.x;
    int tid = threadIdx.x;
    int k = tid >> 5, lane = tid & 31;
    __shared__ float cf[Km];
    const float* row = C1 + (b*Km + k)*64;
    float s = row[lane]*Wf2[lane] + row[32+lane]*Wf2[32+lane];
    #pragma unroll
    for (int o=16;o>0;o>>=1) s += __shfl_xor_sync(0xffffffffu, s, o);
    if (lane == 0) cf[k] = s + bf2[0];
    __syncthreads();
    if (tid < Km){
        float m = cf[0];
        #pragma unroll
        for (int i=1;i<Km;i++) m = fmaxf(m, cf[i]);
        float denom = 0.f;
        #pragma unroll
        for (int i=0;i<Km;i++) denom += expf(cf[i]-m);
        out[PRED_ELEMS + b*Km + tid] = expf(cf[tid]-m)/denom;
    }
}

// ------------------------------- launch -----------------------------------------
extern "C" void kernel_launch(void* const* d_in, const int* in_sizes, int n_in,
                              void* d_out, int out_size)
{
    const float* interaction = (const float*)d_in[0];
    const float* cooperative = (const float*)d_in[1];
    const float* map_ctx     = (const float*)d_in[2];
    const float* mode_q      = (const float*)d_in[3];
    const float* Wc1 = (const float*)d_in[4];
    const float* bc1 = (const float*)d_in[5];
    const float* Wc2 = (const float*)d_in[6];
    const float* bc2 = (const float*)d_in[7];
    const float* Wk1 = (const float*)d_in[8];
    const float* bk1 = (const float*)d_in[9];
    const float* Wk2 = (const float*)d_in[10];
    const float* bk2 = (const float*)d_in[11];
    const float* Wt  = (const float*)d_in[12];
    const float* bt  = (const float*)d_in[13];
    const float* Wv  = (const float*)d_in[18];
    const float* bv  = (const float*)d_in[19];
    const float* Wo  = (const float*)d_in[20];
    const float* bo  = (const float*)d_in[21];
    const float* lng = (const float*)d_in[22];
    const float* lnb = (const float*)d_in[23];
    const float* Wr1 = (const float*)d_in[24];
    const float* br1 = (const float*)d_in[25];
    const float* Wr2 = (const float*)d_in[26];
    const float* br2 = (const float*)d_in[27];
    const float* Wf1 = (const float*)d_in[28];
    const float* bf1 = (const float*)d_in[29];
    const float* Wf2 = (const float*)d_in[30];
    const float* bf2 = (const float*)d_in[31];
    float* out = (float*)d_out;

    float *tmp1, *ctx, *attn, *hbuf, *coarse, *c1, *part, *wvo, *bvo, *zero;
    __half *xh, *xl, *w16;
    cudaGetSymbolAddress((void**)&tmp1,   g_tmp1);
    cudaGetSymbolAddress((void**)&ctx,    g_context);
    cudaGetSymbolAddress((void**)&attn,   g_attn);
    cudaGetSymbolAddress((void**)&hbuf,   g_h);
    cudaGetSymbolAddress((void**)&coarse, g_coarse);
    cudaGetSymbolAddress((void**)&c1,     g_c1);
    cudaGetSymbolAddress((void**)&part,   g_part);
    cudaGetSymbolAddress((void**)&wvo,    g_wvo);
    cudaGetSymbolAddress((void**)&bvo,    g_bvo);
    cudaGetSymbolAddress((void**)&zero,   g_zero512);
    cudaGetSymbolAddress((void**)&xh,     g_xh);
    cudaGetSymbolAddress((void**)&xl,     g_xl);
    cudaGetSymbolAddress((void**)&w16,    g_w16);

    cudaFuncSetAttribute(refine_mma_kernel,
                         cudaFuncAttributeMaxDynamicSharedMemorySize, SMEM_DYN);

    // 0. weight prep (independent)
    prep_w_kernel<<<(Km*Hd*Hd + 255)/256, 256>>>(Wr1, w16);

    // 1. Wvo = Wv @ Wo, bvo = bv@Wo + bo (independent of data chain)
    sgemm64<ACT_NONE,AM_PLAIN><<<dim3(8,8,1),256>>>(Wv,nullptr,nullptr,0,Hd,
                                                    Wo,0,Hd, zero,0, wvo,0,Hd, Hd,Hd,Hd);
    bvo_kernel<<<2,256>>>(bv, Wo, bo, bvo);

    // 2. context_proj (concat fused into A-loader)
    sgemm64<ACT_GELU,AM_CONCAT><<<dim3(8,8,1),256>>>(interaction,cooperative,map_ctx,0,0,
                                                     Wc1,0,Hd, bc1,0, tmp1,0,Hd, Bsz,Hd,3*Hd);
    sgemm64<ACT_NONE,AM_PLAIN><<<dim3(8,8,1),256>>>(tmp1,nullptr,nullptr,0,Hd,
                                                    Wc2,0,Hd, bc2,0, ctx,0,Hd, Bsz,Hd,Hd);

    // 3. attn = ctx @ Wvo + bvo  (uniform attention collapsed + Wv@Wo folded)
    sgemm64<ACT_NONE,AM_PLAIN><<<dim3(8,8,1),256>>>(ctx,nullptr,nullptr,0,Hd,
                                                    wvo,0,Hd, bvo,0, attn,0,Hd, Bsz,Hd,Hd);

    // 4. coarse heads (mode_features fused into A-loader)
    sgemm64<ACT_GELU,AM_CTXQ><<<dim3(16,8,Km),256>>>(ctx,mode_q,nullptr,0,0,
                                                     Wk1,(long long)Hd*H2,H2,
                                                     bk1,H2, hbuf,H2,Km*H2, Bsz,H2,Hd);
    sgemm64<ACT_NONE,AM_PLAIN><<<dim3(2,8,Km),256>>>(hbuf,nullptr,nullptr,H2,Km*H2,
                                                     Wk2,(long long)H2*TO,TO,
                                                     bk2,TO, coarse,TO,Km*TO, Bsz,TO,H2);

    // 5. confidence (mode_features fused)
    sgemm64<ACT_RELU,AM_CONF><<<dim3(1,48,1),256>>>(ctx,mode_q,nullptr,0,0,
                                                    Wf1,0,64, bf1,0, c1,0,64, Bsz*Km,64,Hd);
    conf_softmax_kernel<<<Bsz,192>>>(c1, Wf2, bf2, out);

    // 6. fused traj + residual + LN -> fp16 hi/lo
    traj_ln_kernel<<<NROWS,256>>>(coarse, attn, Wt, bt, lng, lnb, xh, xl);

    // 7. refine GEMM (fp16 2-term) + fused GELU + Wr2 partial reduction
    refine_mma_kernel<<<dim3(4,240,Km),256, SMEM_DYN>>>(xh, xl, w16, br1, Wr2, part);

    // 8. predictions
    finalize_kernel<<<(PRED_ELEMS + 255)/256, 256>>>(coarse, br2, part, out);
}

// round 5
// speedup vs baseline: 4.1278x; 1.3980x over previous
#include <cuda_runtime.h>
#include <cuda_fp16.h>
#include <cstdint>

// Problem constants
#define Bsz 512
#define Hd  512
#define Km  6
#define Tt  60
#define OUTd 2
#define H2  1024
#define TO  120
#define ROWS_PER_MODE (Bsz*Tt)       // 30720
#define NROWS (Km*Bsz*Tt)            // 184320
#define PRED_ELEMS (Bsz*Km*Tt*OUTd)  // 368640

// refine GEMM tiling
#define CH 32                        // k elems per chunk
#define NCHUNK (Hd/CH)               // 16
#define ROWB 80                      // 32 fp16 (64B) + 16B pad
#define PLANE (128*ROWB)             // 10240 B
#define STAGE (2*PLANE)              // A, B = 20480 B
#define SMEM_DYN (2*STAGE)           // 40960 B

// ---------------- scratch (device globals) ------------------------------------
__device__ float g_tmp1[Bsz*Hd];                      // raw c1 out (pre-GELU)
__device__ float g_context[Bsz*Hd];
__device__ float g_attn[Bsz*Hd];
__device__ float g_h[Bsz*Km*H2];                      // raw Wk1 out (pre-GELU)
__device__ float g_coarse[Bsz*Km*TO];
__device__ float g_c1[Bsz*Km*64];
__device__ float g_wvo[Hd*Hd];
__device__ float g_bvo[Hd];
__device__ float g_zero512[Hd];                       // stays zero
__device__ __half g_xh[(long long)NROWS*Hd];          // LN output fp16
__device__ __half g_w16[(long long)Km*Hd*Hd];         // Wr1^T fp16 [k][n][kk]
__device__ float g_part[4LL*NROWS*OUTd];              // per-ntile partials

__device__ __forceinline__ float gelu_exact(float x){
    return 0.5f * x * (1.0f + erff(x * 0.7071067811865476f));
}

#define ACT_NONE 0
#define ACT_GELU 1
#define ACT_RELU 2

// A-source modes
#define AM_PLAIN  0
#define AM_CONCAT 1
#define AM_CTXQ   2   // A[m][k] = ctx[m][k] + mq[bz][k]
#define AM_CONF   3   // A[m][k] = ctx[m/Km][k] + mq[m%Km][k]
#define AM_GELU   4   // A[m][k] = gelu(raw[m][k])

// ---------------- PTX helpers ---------------------------------------------------
__device__ __forceinline__ uint32_t smem_to_u32(const void* p) {
    uint32_t a;
    asm("{ .reg .u64 t; cvta.to.shared.u64 t, %1; cvt.u32.u64 %0, t; }" : "=r"(a) : "l"(p));
    return a;
}
__device__ __forceinline__ uint32_t lds32(uint32_t a){
    uint32_t v;
    asm volatile("ld.shared.b32 %0, [%1];" : "=r"(v) : "r"(a));
    return v;
}
#define CP_ASYNC16(dst, src) \
    asm volatile("cp.async.cg.shared.global [%0], [%1], 16;" :: "r"(dst), "l"(src))
#define CP_COMMIT() asm volatile("cp.async.commit_group;" ::: "memory")
#define CP_WAIT1() asm volatile("cp.async.wait_group 1;" ::: "memory")
#define CP_WAIT0() asm volatile("cp.async.wait_group 0;" ::: "memory")

__device__ __forceinline__ void mma16816(float* c, const uint32_t* a, uint32_t b0, uint32_t b1){
    asm volatile(
        "mma.sync.aligned.m16n8k16.row.col.f32.f16.f16.f32 "
        "{%0,%1,%2,%3}, {%4,%5,%6,%7}, {%8,%9}, {%0,%1,%2,%3};"
        : "+f"(c[0]), "+f"(c[1]), "+f"(c[2]), "+f"(c[3])
        : "r"(a[0]), "r"(a[1]), "r"(a[2]), "r"(a[3]), "r"(b0), "r"(b1));
}

// ---------------- shared A-loader for FFMA GEMMs --------------------------------
template<int AMODE>
__device__ __forceinline__ float4 loadA4g(const float* A, const float* A1, const float* A2,
                                          long long sAb, int lda, int bz, int m, int kk)
{
    if (AMODE == AM_PLAIN)
        return *reinterpret_cast<const float4*>(&A[bz*sAb + (long long)m*lda + kk]);
    if (AMODE == AM_CONCAT) {
        const float* p = (kk < 512) ? A : (kk < 1024) ? A1 : A2;
        return *reinterpret_cast<const float4*>(&p[(long long)m*512 + (kk & 511)]);
    }
    if (AMODE == AM_CTXQ) {
        float4 u = *reinterpret_cast<const float4*>(&A [(long long)m*512 + kk]);
        float4 v = *reinterpret_cast<const float4*>(&A1[(long long)bz*512 + kk]);
        return make_float4(u.x+v.x, u.y+v.y, u.z+v.z, u.w+v.w);
    }
    if (AMODE == AM_CONF) {
        int b = m / Km, km = m - b * Km;
        float4 u = *reinterpret_cast<const float4*>(&A [(long long)b*512 + kk]);
        float4 v = *reinterpret_cast<const float4*>(&A1[(long long)km*512 + kk]);
        return make_float4(u.x+v.x, u.y+v.y, u.z+v.z, u.w+v.w);
    }
    // AM_GELU
    float4 u = *reinterpret_cast<const float4*>(&A[bz*sAb + (long long)m*lda + kk]);
    return make_float4(gelu_exact(u.x), gelu_exact(u.y), gelu_exact(u.z), gelu_exact(u.w));
}

// ---------------- FFMA SGEMM 64x64x16, register-prefetch double buffer ----------
template<int ACT, int AMODE>
__global__ __launch_bounds__(256)
void sgemm64(const float* __restrict__ A, const float* __restrict__ A1,
             const float* __restrict__ A2,
             long long sAb, int lda,
             const float* __restrict__ Bm, long long sBb, int ldb,
             const float* __restrict__ bias, long long sbias,
             float* __restrict__ C, long long sCb, int ldc,
             int M, int N, int Kd)
{
    constexpr int BM=64, BN=64, BK=16;
    __shared__ float As[BK][BM];
    __shared__ float Bs[BK][BN];
    const int bz = blockIdx.z;
    Bm += (long long)bz * sBb;
    C  += (long long)bz * sCb;
    const float* bptr = bias + (long long)bz * sbias;

    const int m0 = blockIdx.y * BM;
    const int n0 = blockIdx.x * BN;
    const int tid = threadIdx.x;
    const int trow = tid >> 4, tcol = tid & 15;
    const int a_r = tid >> 2, a_c = (tid & 3) * 4;
    const int b_r = tid >> 4, b_c = (tid & 15) * 4;

    auto loadB4 = [&](int kk, int n)->float4 {
        if (n + 3 < N)
            return *reinterpret_cast<const float4*>(&Bm[(long long)kk*ldb + n]);
        float4 r;
        r.x = (n+0 < N) ? Bm[(long long)kk*ldb + n+0] : 0.f;
        r.y = (n+1 < N) ? Bm[(long long)kk*ldb + n+1] : 0.f;
        r.z = (n+2 < N) ? Bm[(long long)kk*ldb + n+2] : 0.f;
        r.w = (n+3 < N) ? Bm[(long long)kk*ldb + n+3] : 0.f;
        return r;
    };

    float acc[4][4];
    #pragma unroll
    for (int i=0;i<4;i++)
        #pragma unroll
        for (int j=0;j<4;j++) acc[i][j]=0.f;

    float4 pa = loadA4g<AMODE>(A,A1,A2,sAb,lda,bz, m0 + a_r, a_c);
    float4 pb = loadB4(b_r, n0 + b_c);

    for (int k0 = 0; k0 < Kd; k0 += BK) {
        As[a_c+0][a_r]=pa.x; As[a_c+1][a_r]=pa.y; As[a_c+2][a_r]=pa.z; As[a_c+3][a_r]=pa.w;
        Bs[b_r][b_c+0]=pb.x; Bs[b_r][b_c+1]=pb.y; Bs[b_r][b_c+2]=pb.z; Bs[b_r][b_c+3]=pb.w;
        __syncthreads();
        if (k0 + BK < Kd) {
            pa = loadA4g<AMODE>(A,A1,A2,sAb,lda,bz, m0 + a_r, k0 + BK + a_c);
            pb = loadB4(k0 + BK + b_r, n0 + b_c);
        }
        #pragma unroll
        for (int kk=0; kk<BK; kk++){
            float4 a4 = *reinterpret_cast<const float4*>(&As[kk][trow*4]);
            float4 b4 = *reinterpret_cast<const float4*>(&Bs[kk][tcol*4]);
            float ar[4] = {a4.x,a4.y,a4.z,a4.w};
            float br[4] = {b4.x,b4.y,b4.z,b4.w};
            #pragma unroll
            for (int i=0;i<4;i++)
                #pragma unroll
                for (int j=0;j<4;j++)
                    acc[i][j] = fmaf(ar[i], br[j], acc[i][j]);
        }
        __syncthreads();
    }
    #pragma unroll
    for (int i=0;i<4;i++){
        int m = m0 + trow*4 + i;
        #pragma unroll
        for (int j=0;j<4;j++){
            int n = n0 + tcol*4 + j;
            if (n >= N) continue;
            float val = acc[i][j] + bptr[n];
            if (ACT==ACT_GELU) val = gelu_exact(val);
            else if (ACT==ACT_RELU) val = fmaxf(val, 0.f);
            C[(long long)m*ldc + n] = val;
        }
    }
}

// ---------------- split-K FFMA GEMM, atomic accumulation -------------------------
// grid (N/64, M/64, ksplit); C must be pre-zeroed; bias added by slice z==0.
template<int AMODE>
__global__ __launch_bounds__(256)
void sgemmsk(const float* __restrict__ A, const float* __restrict__ A1,
             const float* __restrict__ A2, int lda,
             const float* __restrict__ Bm, int ldb,
             const float* __restrict__ bias,
             float* __restrict__ C, int ldc,
             int M, int N, int kper)
{
    constexpr int BM=64, BN=64, BK=16;
    __shared__ float As[BK][BM];
    __shared__ float Bs[BK][BN];
    const int z = blockIdx.z;
    const int kbase = z * kper;

    const int m0 = blockIdx.y * BM;
    const int n0 = blockIdx.x * BN;
    const int tid = threadIdx.x;
    const int trow = tid >> 4, tcol = tid & 15;
    const int a_r = tid >> 2, a_c = (tid & 3) * 4;
    const int b_r = tid >> 4, b_c = (tid & 15) * 4;

    float acc[4][4];
    #pragma unroll
    for (int i=0;i<4;i++)
        #pragma unroll
        for (int j=0;j<4;j++) acc[i][j]=0.f;

    float4 pa = loadA4g<AMODE>(A,A1,A2,0,lda,0, m0 + a_r, kbase + a_c);
    float4 pb = *reinterpret_cast<const float4*>(&Bm[(long long)kbase*ldb + b_r*ldb + n0 + b_c]);

    for (int k0 = 0; k0 < kper; k0 += BK) {
        As[a_c+0][a_r]=pa.x; As[a_c+1][a_r]=pa.y; As[a_c+2][a_r]=pa.z; As[a_c+3][a_r]=pa.w;
        Bs[b_r][b_c+0]=pb.x; Bs[b_r][b_c+1]=pb.y; Bs[b_r][b_c+2]=pb.z; Bs[b_r][b_c+3]=pb.w;
        __syncthreads();
        if (k0 + BK < kper) {
            pa = loadA4g<AMODE>(A,A1,A2,0,lda,0, m0 + a_r, kbase + k0 + BK + a_c);
            pb = *reinterpret_cast<const float4*>(&Bm[(long long)(kbase+k0+BK+b_r)*ldb + n0 + b_c]);
        }
        #pragma unroll
        for (int kk=0; kk<BK; kk++){
            float4 a4 = *reinterpret_cast<const float4*>(&As[kk][trow*4]);
            float4 b4 = *reinterpret_cast<const float4*>(&Bs[kk][tcol*4]);
            float ar[4] = {a4.x,a4.y,a4.z,a4.w};
            float br[4] = {b4.x,b4.y,b4.z,b4.w};
            #pragma unroll
            for (int i=0;i<4;i++)
                #pragma unroll
                for (int j=0;j<4;j++)
                    acc[i][j] = fmaf(ar[i], br[j], acc[i][j]);
        }
        __syncthreads();
    }
    #pragma unroll
    for (int i=0;i<4;i++){
        int m = m0 + trow*4 + i;
        #pragma unroll
        for (int j=0;j<4;j++){
            int n = n0 + tcol*4 + j;
            float val = acc[i][j] + ((z == 0) ? bias[n] : 0.f);
            atomicAdd(&C[(long long)m*ldc + n], val);
        }
    }
}

// ---------------- small prep kernels --------------------------------------------
__global__ void bvo_kernel(const float* __restrict__ bv, const float* __restrict__ Wo,
                           const float* __restrict__ bo, float* __restrict__ bvo)
{
    int n = blockIdx.x*blockDim.x + threadIdx.x;
    if (n >= Hd) return;
    float s = bo[n];
    for (int k = 0; k < Hd; k++) s = fmaf(bv[k], Wo[k*Hd + n], s);
    bvo[n] = s;
}

__global__ void prep_w_kernel(const float* __restrict__ Wr1, __half* __restrict__ W16)
{
    long long idx = (long long)blockIdx.x*blockDim.x + threadIdx.x;
    if (idx >= (long long)Km*Hd*Hd) return;
    int kk = idx & 511;
    int n  = (idx >> 9) & 511;
    int k  = idx >> 18;
    W16[idx] = __float2half_rn(Wr1[((long long)k*Hd + kk)*Hd + n]);
}

// Fused: traj = GELU(coarse@Wt + bt); u = traj + attn[b]; x = LN(u); emit fp16
__global__ __launch_bounds__(256)
void traj_ln_kernel(const float* __restrict__ coarse,
                    const float* __restrict__ attn,
                    const float* __restrict__ Wt,
                    const float* __restrict__ bt,
                    const float* __restrict__ ln_g,
                    const float* __restrict__ ln_b,
                    __half* __restrict__ XH)
{
    const int row = blockIdx.x;
    const int k   = row / ROWS_PER_MODE;
    const int rem = row % ROWS_PER_MODE;
    const int b   = rem / Tt;
    const int t   = rem % Tt;
    const float c0 = coarse[((b*Km + k)*Tt + t)*OUTd + 0];
    const float c1 = coarse[((b*Km + k)*Tt + t)*OUTd + 1];
    const int tid = threadIdx.x;

    float u[2];
    float s = 0.f;
    #pragma unroll
    for (int q=0;q<2;q++){
        int h = tid + q*256;
        float pre = fmaf(c0, Wt[h], fmaf(c1, Wt[Hd + h], bt[h]));
        float uu = gelu_exact(pre) + attn[b*Hd + h];
        u[q] = uu;
        s += uu;
    }
    __shared__ float red[8];
    #pragma unroll
    for (int o=16;o>0;o>>=1) s += __shfl_xor_sync(0xffffffffu, s, o);
    if ((tid & 31) == 0) red[tid>>5] = s;
    __syncthreads();
    float mean;
    if (tid < 32) {
        float v = (tid < 8) ? red[tid] : 0.f;
        #pragma unroll
        for (int o=4;o>0;o>>=1) v += __shfl_xor_sync(0xffffffffu, v, o);
        if (tid == 0) red[0] = v * (1.f/512.f);
    }
    __syncthreads();
    mean = red[0];

    float vs = 0.f;
    #pragma unroll
    for (int q=0;q<2;q++){ float d = u[q] - mean; vs += d*d; }
    __syncthreads();
    #pragma unroll
    for (int o=16;o>0;o>>=1) vs += __shfl_xor_sync(0xffffffffu, vs, o);
    if ((tid & 31) == 0) red[tid>>5] = vs;
    __syncthreads();
    if (tid < 32) {
        float v = (tid < 8) ? red[tid] : 0.f;
        #pragma unroll
        for (int o=4;o>0;o>>=1) v += __shfl_xor_sync(0xffffffffu, v, o);
        if (tid == 0) red[0] = rsqrtf(v * (1.f/512.f) + 1e-5f);
    }
    __syncthreads();
    float rstd = red[0];

    long long rbase = (long long)row * Hd;
    #pragma unroll
    for (int q=0;q<2;q++){
        int h = tid + q*256;
        float xv = (u[q] - mean) * rstd * ln_g[h] + ln_b[h];
        XH[rbase + h] = __float2half_rn(xv);
    }
}

// ---------------- refine GEMM (mma.sync fp16 1-term) + fused epilogue -----------
// grid (nt=4, mtile=240, mode=6), 256 threads = 8 warps (4 m x 2 n), warp 32x64
__global__ __launch_bounds__(256)
void refine_mma_kernel(const __half* __restrict__ XH,
                       const __half* __restrict__ W16,
                       const float* __restrict__ br1,
                       const float* __restrict__ Wr2,
                       float* __restrict__ P)
{
    extern __shared__ char smem[];
    const uint32_t sbase = smem_to_u32(smem);
    const int tid  = threadIdx.x;
    const int wid  = tid >> 5;
    const int lane = tid & 31;
    const int wm   = wid & 3;
    const int wn   = wid >> 2;
    const int nt   = blockIdx.x;
    const int m0   = blockIdx.y * 128;
    const int mode = blockIdx.z;

    const __half* xh = XH  + ((long long)mode * ROWS_PER_MODE + m0) * Hd;
    const __half* wv = W16 + ((long long)mode * Hd + nt * 128) * Hd;

    float acc[2][8][4];
    #pragma unroll
    for (int i=0;i<2;i++)
        #pragma unroll
        for (int j=0;j<8;j++)
            #pragma unroll
            for (int q=0;q<4;q++) acc[i][j][q]=0.f;

    const int lr = tid >> 1;
    const int lh = (tid & 1) * 32;
    auto load_chunk = [&](int c, int stage){
        uint32_t sb = sbase + stage * STAGE;
        const __half* srcs[2] = {xh, wv};
        #pragma unroll
        for (int p = 0; p < 2; p++) {
            uint32_t dst = sb + p*PLANE + lr*ROWB + lh;
            const char* g = (const char*)srcs[p] + ((long long)lr*Hd + c*CH)*2 + lh;
            CP_ASYNC16(dst, g);
            CP_ASYNC16(dst + 16, g + 16);
        }
    };

    load_chunk(0, 0);
    CP_COMMIT();

    int buf = 0;
    #pragma unroll 1
    for (int c = 0; c < NCHUNK; c++) {
        if (c + 1 < NCHUNK) { load_chunk(c + 1, buf ^ 1); CP_COMMIT(); CP_WAIT1(); }
        else                { CP_WAIT0(); }
        __syncthreads();

        const uint32_t sb = sbase + buf * STAGE;
        #pragma unroll
        for (int ks = 0; ks < 2; ks++) {
            uint32_t ah[2][4];
            const uint32_t abase = sb + (wm*32 + (lane>>2))*ROWB + ks*32 + (lane&3)*4;
            #pragma unroll
            for (int i=0;i<2;i++){
                uint32_t a = abase + i*16*ROWB;
                ah[i][0] = lds32(a);
                ah[i][1] = lds32(a + 8*ROWB);
                ah[i][2] = lds32(a + 16);
                ah[i][3] = lds32(a + 8*ROWB + 16);
            }
            const uint32_t bbase = sb + PLANE + (wn*64 + (lane>>2))*ROWB + ks*32 + (lane&3)*4;
            #pragma unroll
            for (int j=0;j<8;j++){
                uint32_t b = bbase + j*8*ROWB;
                uint32_t b0 = lds32(b);
                uint32_t b1 = lds32(b + 16);
                #pragma unroll
                for (int i=0;i<2;i++)
                    mma16816(acc[i][j], ah[i], b0, b1);
            }
        }
        __syncthreads();
        buf ^= 1;
    }

    // ---- epilogue: GELU(pre + br1) dot Wr2 over this CTA's 128 n-cols ----
    const float* br1m = br1 + mode * Hd;
    const float* wr2m = Wr2 + mode * Hd * OUTd;
    const int nloc0 = nt*128 + wn*64;

    float p0[2][2], p1[2][2];
    #pragma unroll
    for (int i=0;i<2;i++)
        #pragma unroll
        for (int h2=0;h2<2;h2++){ p0[i][h2]=0.f; p1[i][h2]=0.f; }

    #pragma unroll
    for (int j=0;j<8;j++){
        #pragma unroll
        for (int nn=0;nn<2;nn++){
            const int n = nloc0 + j*8 + (lane&3)*2 + nn;
            const float bv = br1m[n];
            const float w0 = wr2m[n*2+0];
            const float w1 = wr2m[n*2+1];
            #pragma unroll
            for (int i=0;i<2;i++){
                #pragma unroll
                for (int h2=0;h2<2;h2++){
                    float r = gelu_exact(acc[i][j][h2*2+nn] + bv);
                    p0[i][h2] = fmaf(r, w0, p0[i][h2]);
                    p1[i][h2] = fmaf(r, w1, p1[i][h2]);
                }
            }
        }
    }
    #pragma unroll
    for (int i=0;i<2;i++)
        #pragma unroll
        for (int h2=0;h2<2;h2++){
            #pragma unroll
            for (int o=1;o<4;o<<=1){
                p0[i][h2] += __shfl_xor_sync(0xffffffffu, p0[i][h2], o);
                p1[i][h2] += __shfl_xor_sync(0xffffffffu, p1[i][h2], o);
            }
        }

    __syncthreads();
    float* red0 = reinterpret_cast<float*>(smem);
    float* red1 = red0 + 128;
    if (wn == 0 && (lane & 3) == 0){
        #pragma unroll
        for (int i=0;i<2;i++)
            #pragma unroll
            for (int h2=0;h2<2;h2++){
                int rl = wm*32 + i*16 + h2*8 + (lane>>2);
                red0[rl] = p0[i][h2];
                red1[rl] = p1[i][h2];
            }
    }
    __syncthreads();
    if (wn == 1 && (lane & 3) == 0){
        #pragma unroll
        for (int i=0;i<2;i++)
            #pragma unroll
            for (int h2=0;h2<2;h2++){
                int rl = wm*32 + i*16 + h2*8 + (lane>>2);
                long long grow = (long long)mode * ROWS_PER_MODE + m0 + rl;
                long long pidx = ((long long)nt * NROWS + grow) * 2;
                P[pidx + 0] = p0[i][h2] + red0[rl];
                P[pidx + 1] = p1[i][h2] + red1[rl];
            }
    }
}

// predictions = coarse + br2 + sum of 4 ntile partials
__global__ void finalize_kernel(const float* __restrict__ coarse,
                                const float* __restrict__ br2,
                                const float* __restrict__ P,
                                float* __restrict__ out)
{
    int idx = blockIdx.x*blockDim.x + threadIdx.x;
    if (idx >= PRED_ELEMS) return;
    int o = idx & 1;
    int t = (idx >> 1) % Tt;
    int k = ((idx >> 1) / Tt) % Km;
    int b = idx / (2*Tt*Km);
    long long grow = (long long)k * ROWS_PER_MODE + b * Tt + t;
    float s = coarse[idx] + br2[k*2+o];
    #pragma unroll
    for (int nt=0; nt<4; nt++)
        s += P[((long long)nt * NROWS + grow)*2 + o];
    out[idx] = s;
}

// conf head epilogue + softmax
__global__ __launch_bounds__(192)
void conf_softmax_kernel(const float* __restrict__ C1,
                         const float* __restrict__ Wf2,
                         const float* __restrict__ bf2,
                         float* __restrict__ out)
{
    int b = blockIdx.x;
    int tid = threadIdx.x;
    int k = tid >> 5, lane = tid & 31;
    __shared__ float cf[Km];
    const float* row = C1 + (b*Km + k)*64;
    float s = row[lane]*Wf2[lane] + row[32+lane]*Wf2[32+lane];
    #pragma unroll
    for (int o=16;o>0;o>>=1) s += __shfl_xor_sync(0xffffffffu, s, o);
    if (lane == 0) cf[k] = s + bf2[0];
    __syncthreads();
    if (tid < Km){
        float m = cf[0];
        #pragma unroll
        for (int i=1;i<Km;i++) m = fmaxf(m, cf[i]);
        float denom = 0.f;
        #pragma unroll
        for (int i=0;i<Km;i++) denom += expf(cf[i]-m);
        out[PRED_ELEMS + b*Km + tid] = expf(cf[tid]-m)/denom;
    }
}

// ------------------------------- launch ------------------------------------------
extern "C" void kernel_launch(void* const* d_in, const int* in_sizes, int n_in,
                              void* d_out, int out_size)
{
    const float* interaction = (const float*)d_in[0];
    const float* cooperative = (const float*)d_in[1];
    const float* map_ctx     = (const float*)d_in[2];
    const float* mode_q      = (const float*)d_in[3];
    const float* Wc1 = (const float*)d_in[4];
    const float* bc1 = (const float*)d_in[5];
    const float* Wc2 = (const float*)d_in[6];
    const float* bc2 = (const float*)d_in[7];
    const float* Wk1 = (const float*)d_in[8];
    const float* bk1 = (const float*)d_in[9];
    const float* Wk2 = (const float*)d_in[10];
    const float* bk2 = (const float*)d_in[11];
    const float* Wt  = (const float*)d_in[12];
    const float* bt  = (const float*)d_in[13];
    const float* Wv  = (const float*)d_in[18];
    const float* bv  = (const float*)d_in[19];
    const float* Wo  = (const float*)d_in[20];
    const float* bo  = (const float*)d_in[21];
    const float* lng = (const float*)d_in[22];
    const float* lnb = (const float*)d_in[23];
    const float* Wr1 = (const float*)d_in[24];
    const float* br1 = (const float*)d_in[25];
    const float* Wr2 = (const float*)d_in[26];
    const float* br2 = (const float*)d_in[27];
    const float* Wf1 = (const float*)d_in[28];
    const float* bf1 = (const float*)d_in[29];
    const float* Wf2 = (const float*)d_in[30];
    const float* bf2 = (const float*)d_in[31];
    float* out = (float*)d_out;

    float *tmp1, *ctx, *attn, *hbuf, *coarse, *c1, *part, *wvo, *bvo, *zero;
    __half *xh, *w16;
    cudaGetSymbolAddress((void**)&tmp1,   g_tmp1);
    cudaGetSymbolAddress((void**)&ctx,    g_context);
    cudaGetSymbolAddress((void**)&attn,   g_attn);
    cudaGetSymbolAddress((void**)&hbuf,   g_h);
    cudaGetSymbolAddress((void**)&coarse, g_coarse);
    cudaGetSymbolAddress((void**)&c1,     g_c1);
    cudaGetSymbolAddress((void**)&part,   g_part);
    cudaGetSymbolAddress((void**)&wvo,    g_wvo);
    cudaGetSymbolAddress((void**)&bvo,    g_bvo);
    cudaGetSymbolAddress((void**)&zero,   g_zero512);
    cudaGetSymbolAddress((void**)&xh,     g_xh);
    cudaGetSymbolAddress((void**)&w16,    g_w16);

    cudaFuncSetAttribute(refine_mma_kernel,
                         cudaFuncAttributeMaxDynamicSharedMemorySize, SMEM_DYN);

    // zero split-K accumulation targets (graph-capturable async memsets)
    cudaMemsetAsync(wvo,  0, (size_t)Hd*Hd*sizeof(float));
    cudaMemsetAsync(tmp1, 0, (size_t)Bsz*Hd*sizeof(float));
    cudaMemsetAsync(ctx,  0, (size_t)Bsz*Hd*sizeof(float));
    cudaMemsetAsync(attn, 0, (size_t)Bsz*Hd*sizeof(float));

    // 0. weight prep (independent)
    prep_w_kernel<<<(Km*Hd*Hd + 255)/256, 256>>>(Wr1, w16);

    // 1. Wvo = Wv @ Wo (split-K), bvo = bv@Wo + bo
    sgemmsk<AM_PLAIN><<<dim3(8,8,4),256>>>(Wv,nullptr,nullptr,Hd, Wo,Hd, zero,
                                           wvo,Hd, Hd,Hd, Hd/4);
    bvo_kernel<<<2,256>>>(bv, Wo, bo, bvo);

    // 2. context_proj: tmp1 = comb@Wc1 + bc1 (raw); ctx = gelu(tmp1)@Wc2 + bc2
    sgemmsk<AM_CONCAT><<<dim3(8,8,4),256>>>(interaction,cooperative,map_ctx,0,
                                            Wc1,Hd, bc1, tmp1,Hd, Bsz,Hd, (3*Hd)/4);
    sgemmsk<AM_GELU><<<dim3(8,8,4),256>>>(tmp1,nullptr,nullptr,Hd,
                                          Wc2,Hd, bc2, ctx,Hd, Bsz,Hd, Hd/4);

    // 3. attn = ctx @ Wvo + bvo
    sgemmsk<AM_PLAIN><<<dim3(8,8,4),256>>>(ctx,nullptr,nullptr,Hd,
                                           wvo,Hd, bvo, attn,Hd, Bsz,Hd, Hd/4);

    // 4. coarse heads: hbuf = mf@Wk1 + bk1 (raw); coarse = gelu(hbuf)@Wk2 + bk2
    sgemm64<ACT_NONE,AM_CTXQ><<<dim3(16,8,Km),256>>>(ctx,mode_q,nullptr,0,0,
                                                     Wk1,(long long)Hd*H2,H2,
                                                     bk1,H2, hbuf,H2,Km*H2, Bsz,H2,Hd);
    sgemm64<ACT_NONE,AM_GELU><<<dim3(2,8,Km),256>>>(hbuf,nullptr,nullptr,H2,Km*H2,
                                                    Wk2,(long long)H2*TO,TO,
                                                    bk2,TO, coarse,TO,Km*TO, Bsz,TO,H2);

    // 5. confidence
    sgemm64<ACT_RELU,AM_CONF><<<dim3(1,48,1),256>>>(ctx,mode_q,nullptr,0,0,
                                                    Wf1,0,64, bf1,0, c1,0,64, Bsz*Km,64,Hd);
    conf_softmax_kernel<<<Bsz,192>>>(c1, Wf2, bf2, out);

    // 6. fused traj + residual + LN -> fp16
    traj_ln_kernel<<<NROWS,256>>>(coarse, attn, Wt, bt, lng, lnb, xh);

    // 7. refine GEMM (fp16 1-term) + fused GELU + Wr2 partial reduction
    refine_mma_kernel<<<dim3(4,240,Km),256, SMEM_DYN>>>(xh, w16, br1, Wr2, part);

    // 8. predictions
    finalize_kernel<<<(PRED_ELEMS + 255)/256, 256>>>(coarse, br2, part, out);
}